// round 2
// baseline (speedup 1.0000x reference)
#include <cuda_runtime.h>
#include <math.h>
#include <stdint.h>

#define NHID   512
#define HEADS  8
#define NKD    64
#define BB     16
#define SS     511
#define LL     512
#define NNODE  8176      // BB*SS
#define NTOK   8192      // BB*LL
#define EE     131072
#define QKVD   1536
#define FFD    2048

// ----------------------------- scratch (device globals; no allocation) -----
__device__ float g_h   [NTOK*NHID];
__device__ float g_qkv [NTOK*QKVD];
__device__ float g_sc  [(size_t)BB*HEADS*LL*LL];   // 33.5M floats
__device__ float g_o   [NTOK*NHID];
__device__ float g_x   [NTOK*NHID];
__device__ float g_ff  [NTOK*FFD];
__device__ float g_xf  [NNODE*NHID];
__device__ float g_P   [NNODE*NHID];
__device__ float g_Q   [NNODE*NHID];
__device__ float g_T   [2*NNODE*NHID];
__device__ float g_xc  [NNODE*NHID];
__device__ float g_xg  [NNODE*NHID];
__device__ float g_fg  [NNODE*NHID];
__device__ float g_M   [HEADS*NHID*NHID];
__device__ float g_Ncat[HEADS*NHID*64];
__device__ float g_ccat[HEADS*NHID];
__device__ float g_dcat[HEADS*64];
__device__ float g_tvec[2*NNODE];
__device__ float g_sin [2*NNODE];
__device__ float g_sout[2*NNODE];
__device__ float g_inv1[2*NNODE];
__device__ int   g_ind [2*NNODE];
__device__ int   g_outd[2*NNODE];
__device__ int   g_off [2*NNODE];
__device__ int   g_cur [2*NNODE];
__device__ int   g_csr [2*EE];

__constant__ int c_pat[8] = {0,0,1,1,0,0,1,1};

// ----------------------------- generic tiled GEMM --------------------------
struct GP {
    const float *A, *B, *bias, *res;
    float *C;
    int lda, ldb, ldc, ldres;
    int M, N, K;
    float resScale;
    int relu;
    int zDiv;
    long long aO, aI, bO, bI, cO, cI, rO, rI, biasO;
};

template <bool TB>
__global__ void gemm_k(GP p) {
    int zo = blockIdx.z / p.zDiv, zi = blockIdx.z % p.zDiv;
    const float* A  = p.A + zo*p.aO + zi*p.aI;
    const float* Bm = p.B + zo*p.bO + zi*p.bI;
    float*       C  = p.C + zo*p.cO + zi*p.cI;
    const float* bias = p.bias ? (p.bias + zo*p.biasO) : nullptr;
    const float* res  = p.res  ? (p.res  + zo*p.rO + zi*p.rI) : nullptr;

    __shared__ float As[16][64];
    __shared__ float Bs[16][64];
    int tid = threadIdx.x;
    int m0 = blockIdx.x * 64, n0 = blockIdx.y * 64;
    int tx = tid & 15, ty = tid >> 4;
    float acc[4][4] = {};

    int am = tid >> 2;           // 0..63
    int ak = (tid & 3) * 4;      // 0,4,8,12

    for (int k0 = 0; k0 < p.K; k0 += 16) {
        float4 av = make_float4(0.f,0.f,0.f,0.f);
        if (m0 + am < p.M)
            av = *(const float4*)(A + (size_t)(m0+am)*p.lda + k0 + ak);
        As[ak+0][am]=av.x; As[ak+1][am]=av.y; As[ak+2][am]=av.z; As[ak+3][am]=av.w;

        if (!TB) {
            int bk = tid >> 4;              // 0..15
            int bn = (tid & 15) * 4;        // 0..60
            float4 bv = *(const float4*)(Bm + (size_t)(k0+bk)*p.ldb + n0 + bn);
            *(float4*)&Bs[bk][bn] = bv;
        } else {
            int bn = tid >> 2;              // 0..63
            int bk = (tid & 3) * 4;
            float4 bv = *(const float4*)(Bm + (size_t)(n0+bn)*p.ldb + k0 + bk);
            Bs[bk+0][bn]=bv.x; Bs[bk+1][bn]=bv.y; Bs[bk+2][bn]=bv.z; Bs[bk+3][bn]=bv.w;
        }
        __syncthreads();

        #pragma unroll
        for (int k = 0; k < 16; k++) {
            float4 a = *(const float4*)&As[k][ty*4];
            float4 b = *(const float4*)&Bs[k][tx*4];
            acc[0][0]+=a.x*b.x; acc[0][1]+=a.x*b.y; acc[0][2]+=a.x*b.z; acc[0][3]+=a.x*b.w;
            acc[1][0]+=a.y*b.x; acc[1][1]+=a.y*b.y; acc[1][2]+=a.y*b.z; acc[1][3]+=a.y*b.w;
            acc[2][0]+=a.z*b.x; acc[2][1]+=a.z*b.y; acc[2][2]+=a.z*b.z; acc[2][3]+=a.z*b.w;
            acc[3][0]+=a.w*b.x; acc[3][1]+=a.w*b.y; acc[3][2]+=a.w*b.z; acc[3][3]+=a.w*b.w;
        }
        __syncthreads();
    }

    #pragma unroll
    for (int i = 0; i < 4; i++) {
        int m = m0 + ty*4 + i;
        if (m >= p.M) continue;
        #pragma unroll
        for (int j = 0; j < 4; j++) {
            int n = n0 + tx*4 + j;
            float v = acc[i][j];
            if (bias) v += bias[n];
            if (p.relu) v = fmaxf(v, 0.f);
            if (res) v += p.resScale * res[(size_t)m*p.ldres + n];
            C[(size_t)m*p.ldc + n] = v;
        }
    }
}

static void gemm(const float* A, int lda, const float* B, int ldb, float* C, int ldc,
                 int M, int N, int K,
                 const float* bias = nullptr, const float* res = nullptr, int ldres = 0,
                 float resScale = 0.f, int relu = 0, int transB = 0,
                 int z = 1, int zDiv = 1,
                 long long aO=0, long long aI=0, long long bO=0, long long bI=0,
                 long long cO=0, long long cI=0, long long rO=0, long long rI=0,
                 long long biasO=0) {
    GP p;
    p.A=A; p.B=B; p.bias=bias; p.res=res; p.C=C;
    p.lda=lda; p.ldb=ldb; p.ldc=ldc; p.ldres=ldres;
    p.M=M; p.N=N; p.K=K; p.resScale=resScale; p.relu=relu; p.zDiv=zDiv;
    p.aO=aO; p.aI=aI; p.bO=bO; p.bI=bI; p.cO=cO; p.cI=cI; p.rO=rO; p.rI=rI; p.biasO=biasO;
    dim3 grid((M + 63) / 64, N / 64, z);
    if (transB) gemm_k<true><<<grid, 256>>>(p);
    else        gemm_k<false><<<grid, 256>>>(p);
}

// ----------------------------- small kernels -------------------------------
__global__ void k_embed(const float* __restrict__ emb, const float* __restrict__ pos,
                        const int* __restrict__ idxs) {
    int tok = blockIdx.x;            // 0..8191
    int b = tok >> 9, s = tok & 511;
    int id = (s == 0) ? 0 : idxs[b*SS + s - 1];
    const float4* e  = (const float4*)(emb + (size_t)id * NHID);
    const float4* pr = (const float4*)(pos + (size_t)s  * NHID);
    float4* hr = (float4*)(g_h + (size_t)tok * NHID);
    int t = threadIdx.x;             // 128
    float4 a = e[t], c = pr[t];
    hr[t] = make_float4(a.x+c.x, a.y+c.y, a.z+c.z, a.w+c.w);
}

// mask is a JAX bool array marshalled as int32 (harness supports f32/i32/bf16 only)
__global__ void k_softmax(const int* __restrict__ mask) {
    int r = blockIdx.x;                 // ((b*8+h)*512 + i)
    int i = r & 511; int bh = r >> 9; int h = bh & 7; int b = bh >> 3;
    float* row = g_sc + (size_t)r * 512;
    const int* mrow = mask + ((size_t)((b*512 + i)*8 + h)) * 512;
    int t = threadIdx.x;                // 256
    float x0 = row[t]     * 0.125f;
    float x1 = row[t+256] * 0.125f;
    float v0 = mrow[t]     ? x0 : -INFINITY;
    float v1 = mrow[t+256] ? x1 : -INFINITY;
    __shared__ float red[256];
    red[t] = fmaxf(v0, v1); __syncthreads();
    for (int s = 128; s > 0; s >>= 1) { if (t < s) red[t] = fmaxf(red[t], red[t+s]); __syncthreads(); }
    float mx = red[0]; __syncthreads();
    float e0 = __expf(v0 - mx), e1 = __expf(v1 - mx);
    red[t] = e0 + e1; __syncthreads();
    for (int s = 128; s > 0; s >>= 1) { if (t < s) red[t] += red[t+s]; __syncthreads(); }
    float inv = 1.f / red[0];
    row[t] = e0 * inv; row[t+256] = e1 * inv;
}

__global__ void k_ln_add(float* __restrict__ out, const float* __restrict__ inp,
                         const float* __restrict__ base, int hgMap,
                         const float* __restrict__ gw, const float* __restrict__ bw) {
    int n = blockIdx.x;
    const float* xr = inp + (size_t)n * NHID;
    size_t brow;
    if (hgMap) { int b = n / SS, s = n % SS; brow = ((size_t)(b*LL + s + 1)) * NHID; }
    else brow = (size_t)n * NHID;
    int t = threadIdx.x;  // 128
    float x[4];
    #pragma unroll
    for (int i = 0; i < 4; i++) x[i] = xr[t + i*128];
    __shared__ float red[128];
    red[t] = x[0]+x[1]+x[2]+x[3]; __syncthreads();
    for (int s = 64; s > 0; s >>= 1) { if (t < s) red[t] += red[t+s]; __syncthreads(); }
    float mu = red[0] * (1.f/512.f); __syncthreads();
    float d[4], vs = 0.f;
    #pragma unroll
    for (int i = 0; i < 4; i++) { d[i] = x[i] - mu; vs += d[i]*d[i]; }
    red[t] = vs; __syncthreads();
    for (int s = 64; s > 0; s >>= 1) { if (t < s) red[t] += red[t+s]; __syncthreads(); }
    float inv = rsqrtf(red[0] * (1.f/512.f) + 1e-5f);
    #pragma unroll
    for (int i = 0; i < 4; i++) {
        int c = t + i*128;
        out[(size_t)n*NHID + c] = base[brow + c] + d[i]*inv*gw[c] + bw[c];
    }
}

__global__ void k_zg(float* __restrict__ dout) {
    int b = blockIdx.x; int t = threadIdx.x;   // 128
    #pragma unroll
    for (int i = 0; i < 4; i++) {
        int c = t + i*128;
        dout[(size_t)NNODE*NHID + b*NHID + c] = g_h[((size_t)b*LL) * NHID + c];
    }
}

__global__ void k_copyxf() {
    int n = blockIdx.x;
    int b = n / SS, s = n % SS;
    const float4* src = (const float4*)(g_h + ((size_t)(b*LL + s + 1)) * NHID);
    float4* dst = (float4*)(g_xf + (size_t)n * NHID);
    dst[threadIdx.x] = src[threadIdx.x];       // 128 threads
}

__global__ void k_zero_ints() {
    int i = blockIdx.x*blockDim.x + threadIdx.x;
    if (i < 2*NNODE) { g_ind[i] = 0; g_outd[i] = 0; g_cur[i] = 0; }
}

__global__ void k_count(const int* __restrict__ src, const int* __restrict__ dst, int gi) {
    int e = blockIdx.x*blockDim.x + threadIdx.x;
    if (e < EE) {
        atomicAdd(&g_ind [gi*NNODE + dst[e]], 1);
        atomicAdd(&g_outd[gi*NNODE + src[e]], 1);
    }
}

__global__ void k_scan(int gi) {
    __shared__ int sh[1024];
    int t = threadIdx.x;
    int base = gi * NNODE;
    int loc[8]; int sum = 0;
    #pragma unroll
    for (int i = 0; i < 8; i++) {
        int idx = t*8 + i;
        int v = (idx < NNODE) ? g_ind[base + idx] : 0;
        loc[i] = sum; sum += v;
    }
    sh[t] = sum; __syncthreads();
    for (int d = 1; d < 1024; d <<= 1) {
        int v = (t >= d) ? sh[t-d] : 0; __syncthreads();
        sh[t] += v; __syncthreads();
    }
    int pre = (t > 0) ? sh[t-1] : 0;
    #pragma unroll
    for (int i = 0; i < 8; i++) {
        int idx = t*8 + i;
        if (idx < NNODE) g_off[base + idx] = pre + loc[i];
    }
}

__global__ void k_scatter(const int* __restrict__ src, const int* __restrict__ dst, int gi) {
    int e = blockIdx.x*blockDim.x + threadIdx.x;
    if (e < EE) {
        int d = dst[e];
        int p = g_off[gi*NNODE + d] + atomicAdd(&g_cur[gi*NNODE + d], 1);
        g_csr[gi*EE + p] = src[e];
    }
}

__global__ void k_scales() {
    int i = blockIdx.x*blockDim.x + threadIdx.x;
    if (i < 2*NNODE) {
        float in = (float)g_ind[i], od = (float)g_outd[i];
        g_sin [i] = rsqrtf(fmaxf(in, 1.f));
        g_sout[i] = rsqrtf(fmaxf(od, 1.f));
        g_inv1[i] = 1.f / (in + 1.f);
    }
}

// out[n] = (x[n] + sum_in x[src]) / (ind+1)
__global__ void k_prop_sage(const float* __restrict__ x, float* __restrict__ out, int gi) {
    int wid = blockIdx.x * (blockDim.x >> 5) + (threadIdx.x >> 5);
    if (wid >= NNODE) return;
    int lane = threadIdx.x & 31;
    const float4* xr = (const float4*)(x + (size_t)wid * NHID);
    float4 a0 = xr[lane], a1 = xr[lane+32], a2 = xr[lane+64], a3 = xr[lane+96];
    int s = g_off[gi*NNODE + wid], e = s + g_ind[gi*NNODE + wid];
    const int* csr = g_csr + gi*EE;
    for (int j = s; j < e; j++) {
        int sn = csr[j];
        const float4* sr = (const float4*)(x + (size_t)sn * NHID);
        float4 v;
        v = sr[lane];    a0.x+=v.x; a0.y+=v.y; a0.z+=v.z; a0.w+=v.w;
        v = sr[lane+32]; a1.x+=v.x; a1.y+=v.y; a1.z+=v.z; a1.w+=v.w;
        v = sr[lane+64]; a2.x+=v.x; a2.y+=v.y; a2.z+=v.z; a2.w+=v.w;
        v = sr[lane+96]; a3.x+=v.x; a3.y+=v.y; a3.z+=v.z; a3.w+=v.w;
    }
    float sc = g_inv1[gi*NNODE + wid];
    float4* o = (float4*)(out + (size_t)wid * NHID);
    a0.x*=sc; a0.y*=sc; a0.z*=sc; a0.w*=sc; o[lane]    = a0;
    a1.x*=sc; a1.y*=sc; a1.z*=sc; a1.w*=sc; o[lane+32] = a1;
    a2.x*=sc; a2.y*=sc; a2.z*=sc; a2.w*=sc; o[lane+64] = a2;
    a3.x*=sc; a3.y*=sc; a3.z*=sc; a3.w*=sc; o[lane+96] = a3;
}

// T[n] = sum_in s_out[src]*Q[src];  tvec[n] = sum_in s_out[src]
__global__ void k_prop_gc(const float* __restrict__ q, float* __restrict__ outT, int gi) {
    int wid = blockIdx.x * (blockDim.x >> 5) + (threadIdx.x >> 5);
    if (wid >= NNODE) return;
    int lane = threadIdx.x & 31;
    float4 a0 = make_float4(0,0,0,0), a1 = a0, a2 = a0, a3 = a0;
    float ts = 0.f;
    int s = g_off[gi*NNODE + wid], e = s + g_ind[gi*NNODE + wid];
    const int* csr = g_csr + gi*EE;
    for (int j = s; j < e; j++) {
        int sn = csr[j];
        float so = g_sout[gi*NNODE + sn];
        ts += so;
        const float4* sr = (const float4*)(q + (size_t)sn * NHID);
        float4 v;
        v = sr[lane];    a0.x+=v.x*so; a0.y+=v.y*so; a0.z+=v.z*so; a0.w+=v.w*so;
        v = sr[lane+32]; a1.x+=v.x*so; a1.y+=v.y*so; a1.z+=v.z*so; a1.w+=v.w*so;
        v = sr[lane+64]; a2.x+=v.x*so; a2.y+=v.y*so; a2.z+=v.z*so; a2.w+=v.w*so;
        v = sr[lane+96]; a3.x+=v.x*so; a3.y+=v.y*so; a3.z+=v.z*so; a3.w+=v.w*so;
    }
    float4* o = (float4*)(outT + (size_t)wid * NHID);
    o[lane] = a0; o[lane+32] = a1; o[lane+64] = a2; o[lane+96] = a3;
    if (lane == 0) g_tvec[gi*NNODE + wid] = ts;
}

// xc[n,c] = s_in*xc_raw + s_in*t*dcat[c] + gc3_b[c]
__global__ void k_xcepi(const float* __restrict__ gc3b) {
    int n = blockIdx.x; int c = threadIdx.x;   // 512 threads
    int g = c_pat[c >> 6];
    float si = g_sin[g*NNODE + n], tv = g_tvec[g*NNODE + n];
    size_t idx = (size_t)n*NHID + c;
    g_xc[idx] = si * g_xc[idx] + si * tv * g_dcat[c] + gc3b[c];
}

// ----------------------------- host orchestration --------------------------
#define SYM(name, var) { void* _p; cudaGetSymbolAddress(&_p, name); var = (float*)_p; }

extern "C" void kernel_launch(void* const* d_in, const int* in_sizes, int n_in,
                              void* d_out, int out_size) {
    const float* in_embed  = (const float*)d_in[0];
    const float* pos_embed = (const float*)d_in[1];
    const float* qkv_w     = (const float*)d_in[2];
    const float* qkv_b     = (const float*)d_in[3];
    const float* attn_w    = (const float*)d_in[4];
    const float* attn_b    = (const float*)d_in[5];
    const float* ff1_w     = (const float*)d_in[6];
    const float* ff1_b     = (const float*)d_in[7];
    const float* ff2_w     = (const float*)d_in[8];
    const float* ff2_b     = (const float*)d_in[9];
    const float* sage1_w   = (const float*)d_in[10];
    const float* sage1_b   = (const float*)d_in[11];
    const float* sage2_w   = (const float*)d_in[12];
    const float* sage2_b   = (const float*)d_in[13];
    const float* gc3_w     = (const float*)d_in[14];
    const float* gc3_b     = (const float*)d_in[15];
    const float* gff1_w    = (const float*)d_in[16];
    const float* gff1_b    = (const float*)d_in[17];
    const float* gff2_w    = (const float*)d_in[18];
    const float* gff2_b    = (const float*)d_in[19];
    const float* ln_g      = (const float*)d_in[20];
    const float* ln_b      = (const float*)d_in[21];
    const int*   in_idxs   = (const int*)d_in[22];
    const int*   mask      = (const int*)d_in[23];   // bool marshalled as int32
    const int*   gt_src    = (const int*)d_in[24];
    const int*   gt_dst    = (const int*)d_in[25];
    const int*   at_src    = (const int*)d_in[26];
    const int*   at_dst    = (const int*)d_in[27];

    float *h, *qkv, *sc, *o, *x, *ff, *xf, *P, *Q, *T, *xc, *xg, *fg, *Mb, *Nc, *cc, *dc;
    SYM(g_h, h); SYM(g_qkv, qkv); SYM(g_sc, sc); SYM(g_o, o); SYM(g_x, x); SYM(g_ff, ff);
    SYM(g_xf, xf); SYM(g_P, P); SYM(g_Q, Q); SYM(g_T, T); SYM(g_xc, xc); SYM(g_xg, xg);
    SYM(g_fg, fg); SYM(g_M, Mb); SYM(g_Ncat, Nc); SYM(g_ccat, cc); SYM(g_dcat, dc);

    // ---- embedding ----
    k_embed<<<NTOK, 128>>>(in_embed, pos_embed, in_idxs);

    // ---- transformer layers ----
    for (int l = 0; l < 4; l++) {
        // qkv = h @ W + b
        gemm(h, NHID, qkv_w + (size_t)l*NHID*QKVD, QKVD, qkv, QKVD,
             NTOK, QKVD, NHID, qkv_b + l*QKVD);
        // scores = Q @ K^T  (batched over b,h)
        gemm(qkv, QKVD, qkv + NKD, QKVD, sc, LL,
             LL, LL, NKD, nullptr, nullptr, 0, 0.f, 0, /*transB=*/1,
             /*z=*/BB*HEADS, /*zDiv=*/HEADS,
             /*aO=*/(long long)LL*QKVD, /*aI=*/192,
             /*bO=*/(long long)LL*QKVD, /*bI=*/192,
             /*cO=*/(long long)HEADS*LL*LL, /*cI=*/(long long)LL*LL);
        // masked softmax (scale 1/8 fused)
        k_softmax<<<BB*HEADS*LL, 256>>>(mask);
        // o = A @ V
        gemm(sc, LL, qkv + 2*NKD, QKVD, o, NHID,
             LL, NKD, LL, nullptr, nullptr, 0, 0.f, 0, 0,
             BB*HEADS, HEADS,
             (long long)HEADS*LL*LL, (long long)LL*LL,
             (long long)LL*QKVD, 192,
             (long long)LL*NHID, 64);
        // x = 2h + (o @ Wout + b)
        gemm(o, NHID, attn_w + (size_t)l*NHID*NHID, NHID, x, NHID,
             NTOK, NHID, NHID, attn_b + l*NHID, h, NHID, 2.0f);
        // ff = relu(x @ W1 + b1)
        gemm(x, NHID, ff1_w + (size_t)l*NHID*FFD, FFD, ff, FFD,
             NTOK, FFD, NHID, ff1_b + l*FFD, nullptr, 0, 0.f, /*relu=*/1);
        // h = x + (ff @ W2 + b2)
        gemm(ff, FFD, ff2_w + (size_t)l*FFD*NHID, NHID, h, NHID,
             NTOK, NHID, FFD, ff2_b + l*NHID, x, NHID, 1.0f);
    }

    // ---- graph preprocessing ----
    k_zero_ints<<<(2*NNODE + 255)/256, 256>>>();
    k_count<<<EE/256, 256>>>(gt_src, gt_dst, 0);
    k_count<<<EE/256, 256>>>(at_src, at_dst, 1);
    k_scan<<<1, 1024>>>(0);
    k_scan<<<1, 1024>>>(1);
    k_scatter<<<EE/256, 256>>>(gt_src, gt_dst, 0);
    k_scatter<<<EE/256, 256>>>(at_src, at_dst, 1);
    k_scales<<<(2*NNODE + 255)/256, 256>>>();
    k_copyxf<<<NNODE, 128>>>();

    // ---- propagations (3 per graph) ----
    int propBlocks = (NNODE + 7) / 8;   // 8 warps/CTA
    for (int g = 0; g < 2; g++) {
        k_prop_sage<<<propBlocks, 256>>>(xf, P, g);
        k_prop_sage<<<propBlocks, 256>>>(P,  Q, g);
        k_prop_gc  <<<propBlocks, 256>>>(Q,  T + (size_t)g*NNODE*NHID, g);
    }

    // ---- collapse per-head weights: M_i = W1 W2, N_i = M_i W3, c_i, d_i ----
    gemm(sage1_w, NHID, sage2_w, NHID, Mb, NHID, NHID, NHID, NHID,
         nullptr, nullptr, 0, 0.f, 0, 0, HEADS, 1,
         (long long)NHID*NHID, 0, (long long)NHID*NHID, 0, (long long)NHID*NHID, 0);
    gemm(Mb, NHID, gc3_w, 64, Nc, 64, NHID, 64, NHID,
         nullptr, nullptr, 0, 0.f, 0, 0, HEADS, 1,
         (long long)NHID*NHID, 0, (long long)NHID*64, 0, (long long)NHID*64, 0);
    gemm(sage1_b, NHID, sage2_w, NHID, cc, NHID, 1, NHID, NHID,
         sage2_b, nullptr, 0, 0.f, 0, 0, HEADS, 1,
         NHID, 0, (long long)NHID*NHID, 0, NHID, 0, 0, 0, NHID);
    gemm(cc, NHID, gc3_w, 64, dc, 64, 1, 64, NHID,
         nullptr, nullptr, 0, 0.f, 0, 0, HEADS, 1,
         NHID, 0, (long long)NHID*64, 0, 64, 0);

    // ---- xc = [S_in T_g N_i + ...] per head ----
    static const int pat[8] = {0,0,1,1,0,0,1,1};
    for (int i = 0; i < HEADS; i++) {
        gemm(T + (size_t)pat[i]*NNODE*NHID, NHID,
             Nc + (size_t)i*NHID*64, 64,
             xc + i*64, NHID,
             NNODE, 64, NHID);
    }
    k_xcepi<<<NNODE, 512>>>(gc3_b);

    // ---- final: x = hg + LN(xc); ff = relu(x W1+b) W2 + b; zbar = x + LN(ff) ----
    k_ln_add<<<NNODE, 128>>>(xg, xc, h, /*hgMap=*/1, ln_g, ln_b);
    gemm(xg, NHID, gff1_w, NHID, fg, NHID, NNODE, NHID, NHID, gff1_b,
         nullptr, 0, 0.f, /*relu=*/1);
    gemm(fg, NHID, gff2_w, NHID, xc, NHID, NNODE, NHID, NHID, gff2_b);
    k_ln_add<<<NNODE, 128>>>((float*)d_out, xc, xg, /*hgMap=*/0, ln_g, ln_b);

    // ---- zg ----
    if (out_size >= NNODE*NHID + BB*NHID)
        k_zg<<<BB, 128>>>((float*)d_out);
}

// round 3
// speedup vs baseline: 2.6756x; 2.6756x over previous
#include <cuda_runtime.h>
#include <math.h>
#include <stdint.h>

#define NHID   512
#define HEADS  8
#define NKD    64
#define BB     16
#define SS     511
#define LL     512
#define NNODE  8176      // BB*SS
#define NTOK   8192      // BB*LL
#define EE     131072
#define QKVD   1536
#define FFD    2048

// ----------------------------- scratch (device globals; no allocation) -----
__device__ float g_h   [NTOK*NHID];
__device__ float g_qkv [NTOK*QKVD];
__device__ float g_sc  [(size_t)BB*HEADS*LL*LL];
__device__ float g_o   [NTOK*NHID];
__device__ float g_x   [NTOK*NHID];
__device__ float g_ff  [NTOK*FFD];
__device__ float g_xf  [NNODE*NHID];
__device__ float g_P   [NNODE*NHID];
__device__ float g_Q   [NNODE*NHID];
__device__ float g_T   [2*NNODE*NHID];
__device__ float g_xc  [NNODE*NHID];
__device__ float g_xg  [NNODE*NHID];
__device__ float g_fg  [NNODE*NHID];
__device__ float g_M   [HEADS*NHID*NHID];
__device__ float g_Ncat[HEADS*NHID*64];
__device__ float g_ccat[HEADS*NHID];
__device__ float g_dcat[HEADS*64];
__device__ float g_tvec[2*NNODE];
__device__ float g_sin [2*NNODE];
__device__ float g_sout[2*NNODE];
__device__ float g_inv1[2*NNODE];
__device__ int   g_ind [2*NNODE];
__device__ int   g_outd[2*NNODE];
__device__ int   g_off [2*NNODE];
__device__ int   g_cur [2*NNODE];
__device__ int   g_csr [2*EE];

__constant__ int c_pat[8] = {0,0,1,1,0,0,1,1};

// ----------------------------- common GEMM param block ---------------------
struct GP {
    const float *A, *B, *bias, *res;
    float *C;
    int lda, ldb, ldc, ldres;
    int M, N, K;
    float resScale;
    int relu;
    int zDiv;
    int hmode;     // per-head graph GEMM mode: A selected by (z>>1)&1
    long long aO, aI, bO, bI, cO, cI, rO, rI, biasO;
};

// ----------------------------- tf32 helpers --------------------------------
__device__ __forceinline__ unsigned f2tf(float f) {
    unsigned u; asm("cvt.rna.tf32.f32 %0, %1;" : "=r"(u) : "f"(f)); return u;
}
__device__ __forceinline__ uint4 cvt4(float4 v) {
    uint4 r; r.x=f2tf(v.x); r.y=f2tf(v.y); r.z=f2tf(v.z); r.w=f2tf(v.w); return r;
}
__device__ __forceinline__ void ldsm4(unsigned &d0, unsigned &d1, unsigned &d2, unsigned &d3,
                                      unsigned addr) {
    asm volatile("ldmatrix.sync.aligned.m8n8.x4.shared.b16 {%0,%1,%2,%3}, [%4];"
                 : "=r"(d0), "=r"(d1), "=r"(d2), "=r"(d3) : "r"(addr));
}
__device__ __forceinline__ void mma8(float* c, const unsigned* a, const unsigned* b) {
    asm volatile(
        "mma.sync.aligned.m16n8k8.row.col.f32.tf32.tf32.f32 "
        "{%0,%1,%2,%3}, {%4,%5,%6,%7}, {%8,%9}, {%0,%1,%2,%3};"
        : "+f"(c[0]), "+f"(c[1]), "+f"(c[2]), "+f"(c[3])
        : "r"(a[0]), "r"(a[1]), "r"(a[2]), "r"(a[3]), "r"(b[0]), "r"(b[1]));
}

// ----------------------------- tf32 tensor-core GEMM -----------------------
// CTA tile 128 x BN, 8 warps, K-slice 16.
template<int BN, int WGN, bool TB>
__global__ __launch_bounds__(256) void mma_k(GP p) {
    constexpr int WGM = 8 / WGN;
    constexpr int WM  = 128 / WGM;
    constexpr int WN  = BN / WGN;
    constexpr int MF  = WM / 16;
    constexpr int NF  = WN / 8;
    constexpr int AST = 20;        // A smem row stride (words), conflict-free for ldmatrix
    constexpr int BST = BN + 8;    // B smem row stride: =8 mod 32 -> conflict-free frag LDS

    __shared__ unsigned sA[128 * AST];
    __shared__ unsigned sB[16 * BST];

    const float *A, *B; float *C;
    const float *bias = nullptr, *res = nullptr;
    if (p.hmode) {
        int hd = blockIdx.z;
        A = p.A + (((hd >> 1) & 1) ? p.aI : 0);
        B = p.B + (size_t)hd * p.bO;
        C = p.C + (size_t)hd * p.cO;
    } else {
        int zo = blockIdx.z / p.zDiv, zi = blockIdx.z % p.zDiv;
        A = p.A + zo * p.aO + zi * p.aI;
        B = p.B + zo * p.bO + zi * p.bI;
        C = p.C + zo * p.cO + zi * p.cI;
        if (p.bias) bias = p.bias + zo * p.biasO;
        if (p.res)  res  = p.res + zo * p.rO + zi * p.rI;
    }

    int tid = threadIdx.x, lane = tid & 31, warp = tid >> 5;
    int wm = warp / WGN, wn = warp % WGN;
    int m0 = blockIdx.x * 128, n0 = blockIdx.y * BN;

    // A gmem->smem mapping: thread -> (row, 8 k's)
    int ar = tid >> 1, ak = (tid & 1) * 8;
    bool aval = (m0 + ar) < p.M;
    const float* aptr = A + (size_t)(m0 + ar) * p.lda + ak;

    // B gmem->smem mapping
    const float* bptr;
    int bn_t = 0, bk_t = 0, bn4_t = 0;
    if (TB) {            // B is N x K row-major
        bn_t = tid >> 1; bk_t = (tid & 1) * 8;
        bptr = B + (size_t)(n0 + bn_t) * p.ldb + bk_t;
    } else if (BN == 128) {
        bk_t = tid >> 5; bn4_t = (tid & 31) * 4;
        bptr = B + (size_t)bk_t * p.ldb + n0 + bn4_t;
    } else {
        bk_t = tid >> 4; bn4_t = (tid & 15) * 4;
        bptr = B + (size_t)bk_t * p.ldb + n0 + bn4_t;
    }

    float acc[MF][NF][4];
    #pragma unroll
    for (int f = 0; f < MF; f++)
        #pragma unroll
        for (int j = 0; j < NF; j++)
            #pragma unroll
            for (int q = 0; q < 4; q++) acc[f][j][q] = 0.f;

    unsigned sAb = (unsigned)__cvta_generic_to_shared(sA);

    float4 pa0, pa1, pb0, pb1;
    pb0 = pb1 = make_float4(0.f,0.f,0.f,0.f);

    // prefetch stage 0
    if (aval) { pa0 = *(const float4*)(aptr); pa1 = *(const float4*)(aptr + 4); }
    else      { pa0 = pa1 = make_float4(0.f,0.f,0.f,0.f); }
    if (TB)             { pb0 = *(const float4*)(bptr); pb1 = *(const float4*)(bptr + 4); }
    else if (BN == 128) { pb0 = *(const float4*)(bptr); pb1 = *(const float4*)(bptr + (size_t)8 * p.ldb); }
    else                { pb0 = *(const float4*)(bptr); }

    for (int k0 = 0; k0 < p.K; k0 += 16) {
        __syncthreads();
        // store A
        *(uint4*)&sA[ar * AST + ak]     = cvt4(pa0);
        *(uint4*)&sA[ar * AST + ak + 4] = cvt4(pa1);
        // store B (k-major rows, stride BST)
        if (TB) {
            sB[(bk_t + 0) * BST + bn_t] = f2tf(pb0.x);
            sB[(bk_t + 1) * BST + bn_t] = f2tf(pb0.y);
            sB[(bk_t + 2) * BST + bn_t] = f2tf(pb0.z);
            sB[(bk_t + 3) * BST + bn_t] = f2tf(pb0.w);
            sB[(bk_t + 4) * BST + bn_t] = f2tf(pb1.x);
            sB[(bk_t + 5) * BST + bn_t] = f2tf(pb1.y);
            sB[(bk_t + 6) * BST + bn_t] = f2tf(pb1.z);
            sB[(bk_t + 7) * BST + bn_t] = f2tf(pb1.w);
        } else if (BN == 128) {
            *(uint4*)&sB[bk_t * BST + bn4_t]       = cvt4(pb0);
            *(uint4*)&sB[(bk_t + 8) * BST + bn4_t] = cvt4(pb1);
        } else {
            *(uint4*)&sB[bk_t * BST + bn4_t] = cvt4(pb0);
        }
        __syncthreads();

        // prefetch next stage (hidden behind MMA)
        if (k0 + 16 < p.K) {
            if (aval) { pa0 = *(const float4*)(aptr + k0 + 16); pa1 = *(const float4*)(aptr + k0 + 20); }
            if (TB)             { pb0 = *(const float4*)(bptr + k0 + 16); pb1 = *(const float4*)(bptr + k0 + 20); }
            else if (BN == 128) { pb0 = *(const float4*)(bptr + (size_t)(k0 + 16) * p.ldb);
                                  pb1 = *(const float4*)(bptr + (size_t)(k0 + 24) * p.ldb); }
            else                { pb0 = *(const float4*)(bptr + (size_t)(k0 + 16) * p.ldb); }
        }

        #pragma unroll
        for (int kk = 0; kk < 16; kk += 8) {
            unsigned bfr[NF][2];
            #pragma unroll
            for (int j = 0; j < NF; j++) {
                int nb = wn * WN + j * 8 + (lane >> 2);
                bfr[j][0] = sB[(kk + (lane & 3)) * BST + nb];
                bfr[j][1] = sB[(kk + 4 + (lane & 3)) * BST + nb];
            }
            #pragma unroll
            for (int f = 0; f < MF; f++) {
                int mi = lane >> 3, r = lane & 7;
                int row = wm * WM + f * 16 + r + (mi & 1) * 8;
                unsigned addr = sAb + 4u * (unsigned)(row * AST + kk + (mi >> 1) * 4);
                unsigned afr[4];
                ldsm4(afr[0], afr[1], afr[2], afr[3], addr);
                #pragma unroll
                for (int j = 0; j < NF; j++) mma8(acc[f][j], afr, bfr[j]);
            }
        }
    }

    // epilogue: bias -> relu -> + resScale*res, write float2 pairs
    #pragma unroll
    for (int f = 0; f < MF; f++) {
        int r0 = m0 + wm * WM + f * 16 + (lane >> 2);
        int r1 = r0 + 8;
        #pragma unroll
        for (int j = 0; j < NF; j++) {
            int col = n0 + wn * WN + j * 8 + 2 * (lane & 3);
            float b0 = 0.f, b1 = 0.f;
            if (bias) { b0 = bias[col]; b1 = bias[col + 1]; }
            float v0 = acc[f][j][0] + b0, v1 = acc[f][j][1] + b1;
            float v2 = acc[f][j][2] + b0, v3 = acc[f][j][3] + b1;
            if (p.relu) {
                v0 = fmaxf(v0, 0.f); v1 = fmaxf(v1, 0.f);
                v2 = fmaxf(v2, 0.f); v3 = fmaxf(v3, 0.f);
            }
            if (r0 < p.M) {
                if (res) {
                    v0 += p.resScale * res[(size_t)r0 * p.ldres + col];
                    v1 += p.resScale * res[(size_t)r0 * p.ldres + col + 1];
                }
                *(float2*)&C[(size_t)r0 * p.ldc + col] = make_float2(v0, v1);
            }
            if (r1 < p.M) {
                if (res) {
                    v2 += p.resScale * res[(size_t)r1 * p.ldres + col];
                    v3 += p.resScale * res[(size_t)r1 * p.ldres + col + 1];
                }
                *(float2*)&C[(size_t)r1 * p.ldc + col] = make_float2(v2, v3);
            }
        }
    }
}

static void mgemm(const float* A, int lda, const float* B, int ldb, float* C, int ldc,
                  int M, int N, int K,
                  const float* bias = nullptr, const float* res = nullptr, int ldres = 0,
                  float resScale = 0.f, int relu = 0, int transB = 0,
                  int z = 1, int zDiv = 1,
                  long long aO=0, long long aI=0, long long bO=0, long long bI=0,
                  long long cO=0, long long cI=0, long long rO=0, long long rI=0,
                  long long biasO=0, int hmode = 0) {
    GP p;
    p.A=A; p.B=B; p.bias=bias; p.res=res; p.C=C;
    p.lda=lda; p.ldb=ldb; p.ldc=ldc; p.ldres=ldres;
    p.M=M; p.N=N; p.K=K; p.resScale=resScale; p.relu=relu; p.zDiv=zDiv; p.hmode=hmode;
    p.aO=aO; p.aI=aI; p.bO=bO; p.bI=bI; p.cO=cO; p.cI=cI; p.rO=rO; p.rI=rI; p.biasO=biasO;
    if (transB) {
        dim3 grid((M + 127) / 128, N / 128, z);
        mma_k<128, 4, true><<<grid, 256>>>(p);
    } else if (N % 128 == 0) {
        dim3 grid((M + 127) / 128, N / 128, z);
        mma_k<128, 4, false><<<grid, 256>>>(p);
    } else {
        dim3 grid((M + 127) / 128, N / 64, z);
        mma_k<64, 2, false><<<grid, 256>>>(p);
    }
}

// ----------------------------- small FFMA GEMM (tiny M=1 cases) ------------
__global__ void gemm1_k(GP p) {
    // M==1: one block per 64 output cols per z; 64 threads
    int zo = blockIdx.z;
    const float* A = p.A + zo * p.aO;
    const float* B = p.B + zo * p.bO;
    float* C = p.C + zo * p.cO;
    const float* bias = p.bias ? p.bias + zo * p.biasO : nullptr;
    int n = blockIdx.x * 64 + threadIdx.x;
    if (n >= p.N) return;
    float s = 0.f;
    for (int k = 0; k < p.K; k++) s += A[k] * B[(size_t)k * p.ldb + n];
    if (bias) s += bias[n];
    C[n] = s;
}

// ----------------------------- small kernels -------------------------------
__global__ void k_embed(const float* __restrict__ emb, const float* __restrict__ pos,
                        const int* __restrict__ idxs) {
    int tok = blockIdx.x;
    int b = tok >> 9, s = tok & 511;
    int id = (s == 0) ? 0 : idxs[b*SS + s - 1];
    const float4* e  = (const float4*)(emb + (size_t)id * NHID);
    const float4* pr = (const float4*)(pos + (size_t)s  * NHID);
    float4* hr = (float4*)(g_h + (size_t)tok * NHID);
    int t = threadIdx.x;
    float4 a = e[t], c = pr[t];
    hr[t] = make_float4(a.x+c.x, a.y+c.y, a.z+c.z, a.w+c.w);
}

// warp-per-row masked softmax (mask = bool marshalled as int32)
__global__ void k_softmax(const int* __restrict__ mask) {
    int r = blockIdx.x * 8 + (threadIdx.x >> 5);
    int lane = threadIdx.x & 31;
    int i = r & 511; int bh = r >> 9; int h = bh & 7; int b = bh >> 3;
    float4* rowv = (float4*)(g_sc + (size_t)r * 512);
    const int4* mv = (const int4*)(mask + ((size_t)((b*512 + i)*8 + h)) * 512);
    float v[16];
    float mx = -INFINITY;
    #pragma unroll
    for (int c = 0; c < 4; c++) {
        float4 x = rowv[lane + c*32];
        int4 m = mv[lane + c*32];
        v[c*4+0] = m.x ? x.x * 0.125f : -INFINITY;
        v[c*4+1] = m.y ? x.y * 0.125f : -INFINITY;
        v[c*4+2] = m.z ? x.z * 0.125f : -INFINITY;
        v[c*4+3] = m.w ? x.w * 0.125f : -INFINITY;
        mx = fmaxf(mx, fmaxf(fmaxf(v[c*4], v[c*4+1]), fmaxf(v[c*4+2], v[c*4+3])));
    }
    #pragma unroll
    for (int s = 16; s > 0; s >>= 1) mx = fmaxf(mx, __shfl_xor_sync(0xffffffffu, mx, s));
    float sum = 0.f;
    #pragma unroll
    for (int c = 0; c < 16; c++) { v[c] = __expf(v[c] - mx); sum += v[c]; }
    #pragma unroll
    for (int s = 16; s > 0; s >>= 1) sum += __shfl_xor_sync(0xffffffffu, sum, s);
    float inv = 1.f / sum;
    #pragma unroll
    for (int c = 0; c < 4; c++)
        rowv[lane + c*32] = make_float4(v[c*4]*inv, v[c*4+1]*inv, v[c*4+2]*inv, v[c*4+3]*inv);
}

__global__ void k_ln_add(float* __restrict__ out, const float* __restrict__ inp,
                         const float* __restrict__ base, int hgMap,
                         const float* __restrict__ gw, const float* __restrict__ bw) {
    int n = blockIdx.x;
    const float* xr = inp + (size_t)n * NHID;
    size_t brow;
    if (hgMap) { int b = n / SS, s = n % SS; brow = ((size_t)(b*LL + s + 1)) * NHID; }
    else brow = (size_t)n * NHID;
    int t = threadIdx.x;  // 128
    float x[4];
    #pragma unroll
    for (int i = 0; i < 4; i++) x[i] = xr[t + i*128];
    __shared__ float red[128];
    red[t] = x[0]+x[1]+x[2]+x[3]; __syncthreads();
    for (int s = 64; s > 0; s >>= 1) { if (t < s) red[t] += red[t+s]; __syncthreads(); }
    float mu = red[0] * (1.f/512.f); __syncthreads();
    float d[4], vs = 0.f;
    #pragma unroll
    for (int i = 0; i < 4; i++) { d[i] = x[i] - mu; vs += d[i]*d[i]; }
    red[t] = vs; __syncthreads();
    for (int s = 64; s > 0; s >>= 1) { if (t < s) red[t] += red[t+s]; __syncthreads(); }
    float inv = rsqrtf(red[0] * (1.f/512.f) + 1e-5f);
    #pragma unroll
    for (int i = 0; i < 4; i++) {
        int c = t + i*128;
        out[(size_t)n*NHID + c] = base[brow + c] + d[i]*inv*gw[c] + bw[c];
    }
}

__global__ void k_zg(float* __restrict__ dout) {
    int b = blockIdx.x; int t = threadIdx.x;
    #pragma unroll
    for (int i = 0; i < 4; i++) {
        int c = t + i*128;
        dout[(size_t)NNODE*NHID + b*NHID + c] = g_h[((size_t)b*LL) * NHID + c];
    }
}

__global__ void k_copyxf() {
    int n = blockIdx.x;
    int b = n / SS, s = n % SS;
    const float4* src = (const float4*)(g_h + ((size_t)(b*LL + s + 1)) * NHID);
    float4* dst = (float4*)(g_xf + (size_t)n * NHID);
    dst[threadIdx.x] = src[threadIdx.x];
}

__global__ void k_zero_ints() {
    int i = blockIdx.x*blockDim.x + threadIdx.x;
    if (i < 2*NNODE) { g_ind[i] = 0; g_outd[i] = 0; g_cur[i] = 0; }
}

__global__ void k_count(const int* __restrict__ src, const int* __restrict__ dst, int gi) {
    int e = blockIdx.x*blockDim.x + threadIdx.x;
    if (e < EE) {
        atomicAdd(&g_ind [gi*NNODE + dst[e]], 1);
        atomicAdd(&g_outd[gi*NNODE + src[e]], 1);
    }
}

__global__ void k_scan(int gi) {
    __shared__ int sh[1024];
    int t = threadIdx.x;
    int base = gi * NNODE;
    int loc[8]; int sum = 0;
    #pragma unroll
    for (int i = 0; i < 8; i++) {
        int idx = t*8 + i;
        int v = (idx < NNODE) ? g_ind[base + idx] : 0;
        loc[i] = sum; sum += v;
    }
    sh[t] = sum; __syncthreads();
    for (int d = 1; d < 1024; d <<= 1) {
        int v = (t >= d) ? sh[t-d] : 0; __syncthreads();
        sh[t] += v; __syncthreads();
    }
    int pre = (t > 0) ? sh[t-1] : 0;
    #pragma unroll
    for (int i = 0; i < 8; i++) {
        int idx = t*8 + i;
        if (idx < NNODE) g_off[base + idx] = pre + loc[i];
    }
}

__global__ void k_scatter(const int* __restrict__ src, const int* __restrict__ dst, int gi) {
    int e = blockIdx.x*blockDim.x + threadIdx.x;
    if (e < EE) {
        int d = dst[e];
        int p = g_off[gi*NNODE + d] + atomicAdd(&g_cur[gi*NNODE + d], 1);
        g_csr[gi*EE + p] = src[e];
    }
}

__global__ void k_scales() {
    int i = blockIdx.x*blockDim.x + threadIdx.x;
    if (i < 2*NNODE) {
        float in = (float)g_ind[i], od = (float)g_outd[i];
        g_sin [i] = rsqrtf(fmaxf(in, 1.f));
        g_sout[i] = rsqrtf(fmaxf(od, 1.f));
        g_inv1[i] = 1.f / (in + 1.f);
    }
}

__global__ void k_prop_sage(const float* __restrict__ x, float* __restrict__ out, int gi) {
    int wid = blockIdx.x * (blockDim.x >> 5) + (threadIdx.x >> 5);
    if (wid >= NNODE) return;
    int lane = threadIdx.x & 31;
    const float4* xr = (const float4*)(x + (size_t)wid * NHID);
    float4 a0 = xr[lane], a1 = xr[lane+32], a2 = xr[lane+64], a3 = xr[lane+96];
    int s = g_off[gi*NNODE + wid], e = s + g_ind[gi*NNODE + wid];
    const int* csr = g_csr + gi*EE;
    for (int j = s; j < e; j++) {
        int sn = csr[j];
        const float4* sr = (const float4*)(x + (size_t)sn * NHID);
        float4 v;
        v = sr[lane];    a0.x+=v.x; a0.y+=v.y; a0.z+=v.z; a0.w+=v.w;
        v = sr[lane+32]; a1.x+=v.x; a1.y+=v.y; a1.z+=v.z; a1.w+=v.w;
        v = sr[lane+64]; a2.x+=v.x; a2.y+=v.y; a2.z+=v.z; a2.w+=v.w;
        v = sr[lane+96]; a3.x+=v.x; a3.y+=v.y; a3.z+=v.z; a3.w+=v.w;
    }
    float sc = g_inv1[gi*NNODE + wid];
    float4* o = (float4*)(out + (size_t)wid * NHID);
    a0.x*=sc; a0.y*=sc; a0.z*=sc; a0.w*=sc; o[lane]    = a0;
    a1.x*=sc; a1.y*=sc; a1.z*=sc; a1.w*=sc; o[lane+32] = a1;
    a2.x*=sc; a2.y*=sc; a2.z*=sc; a2.w*=sc; o[lane+64] = a2;
    a3.x*=sc; a3.y*=sc; a3.z*=sc; a3.w*=sc; o[lane+96] = a3;
}

__global__ void k_prop_gc(const float* __restrict__ q, float* __restrict__ outT, int gi) {
    int wid = blockIdx.x * (blockDim.x >> 5) + (threadIdx.x >> 5);
    if (wid >= NNODE) return;
    int lane = threadIdx.x & 31;
    float4 a0 = make_float4(0,0,0,0), a1 = a0, a2 = a0, a3 = a0;
    float ts = 0.f;
    int s = g_off[gi*NNODE + wid], e = s + g_ind[gi*NNODE + wid];
    const int* csr = g_csr + gi*EE;
    for (int j = s; j < e; j++) {
        int sn = csr[j];
        float so = g_sout[gi*NNODE + sn];
        ts += so;
        const float4* sr = (const float4*)(q + (size_t)sn * NHID);
        float4 v;
        v = sr[lane];    a0.x+=v.x*so; a0.y+=v.y*so; a0.z+=v.z*so; a0.w+=v.w*so;
        v = sr[lane+32]; a1.x+=v.x*so; a1.y+=v.y*so; a1.z+=v.z*so; a1.w+=v.w*so;
        v = sr[lane+64]; a2.x+=v.x*so; a2.y+=v.y*so; a2.z+=v.z*so; a2.w+=v.w*so;
        v = sr[lane+96]; a3.x+=v.x*so; a3.y+=v.y*so; a3.z+=v.z*so; a3.w+=v.w*so;
    }
    float4* o = (float4*)(outT + (size_t)wid * NHID);
    o[lane] = a0; o[lane+32] = a1; o[lane+64] = a2; o[lane+96] = a3;
    if (lane == 0) g_tvec[gi*NNODE + wid] = ts;
}

__global__ void k_xcepi(const float* __restrict__ gc3b) {
    int n = blockIdx.x; int c = threadIdx.x;
    int g = c_pat[c >> 6];
    float si = g_sin[g*NNODE + n], tv = g_tvec[g*NNODE + n];
    size_t idx = (size_t)n*NHID + c;
    g_xc[idx] = si * g_xc[idx] + si * tv * g_dcat[c] + gc3b[c];
}

// ----------------------------- host orchestration --------------------------
#define SYM(name, var) { void* _p; cudaGetSymbolAddress(&_p, name); var = (float*)_p; }

extern "C" void kernel_launch(void* const* d_in, const int* in_sizes, int n_in,
                              void* d_out, int out_size) {
    const float* in_embed  = (const float*)d_in[0];
    const float* pos_embed = (const float*)d_in[1];
    const float* qkv_w     = (const float*)d_in[2];
    const float* qkv_b     = (const float*)d_in[3];
    const float* attn_w    = (const float*)d_in[4];
    const float* attn_b    = (const float*)d_in[5];
    const float* ff1_w     = (const float*)d_in[6];
    const float* ff1_b     = (const float*)d_in[7];
    const float* ff2_w     = (const float*)d_in[8];
    const float* ff2_b     = (const float*)d_in[9];
    const float* sage1_w   = (const float*)d_in[10];
    const float* sage1_b   = (const float*)d_in[11];
    const float* sage2_w   = (const float*)d_in[12];
    const float* sage2_b   = (const float*)d_in[13];
    const float* gc3_w     = (const float*)d_in[14];
    const float* gc3_b     = (const float*)d_in[15];
    const float* gff1_w    = (const float*)d_in[16];
    const float* gff1_b    = (const float*)d_in[17];
    const float* gff2_w    = (const float*)d_in[18];
    const float* gff2_b    = (const float*)d_in[19];
    const float* ln_g      = (const float*)d_in[20];
    const float* ln_b      = (const float*)d_in[21];
    const int*   in_idxs   = (const int*)d_in[22];
    const int*   mask      = (const int*)d_in[23];   // bool marshalled as int32
    const int*   gt_src    = (const int*)d_in[24];
    const int*   gt_dst    = (const int*)d_in[25];
    const int*   at_src    = (const int*)d_in[26];
    const int*   at_dst    = (const int*)d_in[27];

    float *h, *qkv, *sc, *o, *x, *ff, *xf, *P, *Q, *T, *xc, *xg, *fg, *Mb, *Nc, *cc, *dc;
    SYM(g_h, h); SYM(g_qkv, qkv); SYM(g_sc, sc); SYM(g_o, o); SYM(g_x, x); SYM(g_ff, ff);
    SYM(g_xf, xf); SYM(g_P, P); SYM(g_Q, Q); SYM(g_T, T); SYM(g_xc, xc); SYM(g_xg, xg);
    SYM(g_fg, fg); SYM(g_M, Mb); SYM(g_Ncat, Nc); SYM(g_ccat, cc); SYM(g_dcat, dc);

    // ---- embedding ----
    k_embed<<<NTOK, 128>>>(in_embed, pos_embed, in_idxs);

    // ---- transformer layers ----
    for (int l = 0; l < 4; l++) {
        // qkv = h @ W + b
        mgemm(h, NHID, qkv_w + (size_t)l*NHID*QKVD, QKVD, qkv, QKVD,
              NTOK, QKVD, NHID, qkv_b + l*QKVD);
        // scores = Q @ K^T  (batched over b,h)
        mgemm(qkv, QKVD, qkv + NKD, QKVD, sc, LL,
              LL, LL, NKD, nullptr, nullptr, 0, 0.f, 0, /*transB=*/1,
              BB*HEADS, HEADS,
              (long long)LL*QKVD, 192,
              (long long)LL*QKVD, 192,
              (long long)HEADS*LL*LL, (long long)LL*LL);
        // masked softmax (scale 1/8 fused)
        k_softmax<<<BB*HEADS*LL/8, 256>>>(mask);
        // o = A @ V
        mgemm(sc, LL, qkv + 2*NKD, QKVD, o, NHID,
              LL, NKD, LL, nullptr, nullptr, 0, 0.f, 0, 0,
              BB*HEADS, HEADS,
              (long long)HEADS*LL*LL, (long long)LL*LL,
              (long long)LL*QKVD, 192,
              (long long)LL*NHID, 64);
        // x = 2h + (o @ Wout + b)
        mgemm(o, NHID, attn_w + (size_t)l*NHID*NHID, NHID, x, NHID,
              NTOK, NHID, NHID, attn_b + l*NHID, h, NHID, 2.0f);
        // ff = relu(x @ W1 + b1)
        mgemm(x, NHID, ff1_w + (size_t)l*NHID*FFD, FFD, ff, FFD,
              NTOK, FFD, NHID, ff1_b + l*FFD, nullptr, 0, 0.f, /*relu=*/1);
        // h = x + (ff @ W2 + b2)
        mgemm(ff, FFD, ff2_w + (size_t)l*FFD*NHID, NHID, h, NHID,
              NTOK, NHID, FFD, ff2_b + l*NHID, x, NHID, 1.0f);
    }

    // ---- graph preprocessing ----
    k_zero_ints<<<(2*NNODE + 255)/256, 256>>>();
    k_count<<<EE/256, 256>>>(gt_src, gt_dst, 0);
    k_count<<<EE/256, 256>>>(at_src, at_dst, 1);
    k_scan<<<1, 1024>>>(0);
    k_scan<<<1, 1024>>>(1);
    k_scatter<<<EE/256, 256>>>(gt_src, gt_dst, 0);
    k_scatter<<<EE/256, 256>>>(at_src, at_dst, 1);
    k_scales<<<(2*NNODE + 255)/256, 256>>>();
    k_copyxf<<<NNODE, 128>>>();

    // ---- propagations (3 per graph) ----
    int propBlocks = (NNODE + 7) / 8;
    for (int g = 0; g < 2; g++) {
        k_prop_sage<<<propBlocks, 256>>>(xf, P, g);
        k_prop_sage<<<propBlocks, 256>>>(P,  Q, g);
        k_prop_gc  <<<propBlocks, 256>>>(Q,  T + (size_t)g*NNODE*NHID, g);
    }

    // ---- collapse per-head weights: M_i = W1 W2, N_i = M_i W3, c_i, d_i ----
    mgemm(sage1_w, NHID, sage2_w, NHID, Mb, NHID, NHID, NHID, NHID,
          nullptr, nullptr, 0, 0.f, 0, 0, HEADS, 1,
          (long long)NHID*NHID, 0, (long long)NHID*NHID, 0, (long long)NHID*NHID, 0);
    mgemm(Mb, NHID, gc3_w, 64, Nc, 64, NHID, 64, NHID,
          nullptr, nullptr, 0, 0.f, 0, 0, HEADS, 1,
          (long long)NHID*NHID, 0, (long long)NHID*64, 0, (long long)NHID*64, 0);
    {
        // cc_i = b1_i @ W2_i + b2_i  (M=1, FFMA path)
        GP p; p.A=sage1_b; p.B=sage2_w; p.bias=sage2_b; p.res=nullptr; p.C=cc;
        p.lda=NHID; p.ldb=NHID; p.ldc=NHID; p.ldres=0;
        p.M=1; p.N=NHID; p.K=NHID; p.resScale=0; p.relu=0; p.zDiv=1; p.hmode=0;
        p.aO=NHID; p.bO=(long long)NHID*NHID; p.cO=NHID; p.biasO=NHID;
        p.aI=p.bI=p.cI=p.rO=p.rI=0;
        gemm1_k<<<dim3((NHID+63)/64,1,HEADS), 64>>>(p);
    }
    {
        // dc_i = cc_i @ W3_i  (M=1)
        GP p; p.A=cc; p.B=gc3_w; p.bias=nullptr; p.res=nullptr; p.C=dc;
        p.lda=NHID; p.ldb=64; p.ldc=64; p.ldres=0;
        p.M=1; p.N=64; p.K=NHID; p.resScale=0; p.relu=0; p.zDiv=1; p.hmode=0;
        p.aO=NHID; p.bO=(long long)NHID*64; p.cO=64; p.biasO=0;
        p.aI=p.bI=p.cI=p.rO=p.rI=0;
        gemm1_k<<<dim3(1,1,HEADS), 64>>>(p);
    }

    // ---- xc per head: one launch, A = T[(z>>1)&1], via hmode ----
    mgemm(T, NHID, Nc, 64, xc, NHID,
          NNODE, 64, NHID, nullptr, nullptr, 0, 0.f, 0, 0,
          HEADS, 1,
          0, (long long)NNODE*NHID,           // aI = T graph stride (selected by (z>>1)&1)
          (long long)NHID*64, 0,              // bO = per-head Nc stride
          64, 0, 0, 0, 0, /*hmode=*/1);
    k_xcepi<<<NNODE, 512>>>(gc3_b);

    // ---- final: x = hg + LN(xc); ff = relu(x W1+b) W2 + b; zbar = x + LN(ff) ----
    k_ln_add<<<NNODE, 128>>>(xg, xc, h, /*hgMap=*/1, ln_g, ln_b);
    mgemm(xg, NHID, gff1_w, NHID, fg, NHID, NNODE, NHID, NHID, gff1_b,
          nullptr, 0, 0.f, /*relu=*/1);
    mgemm(fg, NHID, gff2_w, NHID, xc, NHID, NNODE, NHID, NHID, gff2_b);
    k_ln_add<<<NNODE, 128>>>((float*)d_out, xc, xg, /*hgMap=*/0, ln_g, ln_b);

    // ---- zg ----
    if (out_size >= NNODE*NHID + BB*NHID)
        k_zg<<<BB, 128>>>((float*)d_out);
}

// round 4
// speedup vs baseline: 2.8798x; 1.0763x over previous
#include <cuda_runtime.h>
#include <math.h>
#include <stdint.h>

#define NHID   512
#define HEADS  8
#define NKD    64
#define BB     16
#define SS     511
#define LL     512
#define NNODE  8176      // BB*SS
#define NTOK   8192      // BB*LL
#define EE     131072
#define QKVD   1536
#define FFD    2048

// ----------------------------- scratch (device globals; no allocation) -----
__device__ float g_h   [NTOK*NHID];
__device__ float g_qkv [NTOK*QKVD];
__device__ float g_o   [NTOK*NHID];
__device__ float g_x   [NTOK*NHID];
__device__ float g_ff  [NTOK*FFD];
__device__ float g_xf  [NNODE*NHID];
__device__ float g_P   [NNODE*NHID];
__device__ float g_Q   [NNODE*NHID];
__device__ float g_T   [2*NNODE*NHID];
__device__ float g_xc  [NNODE*NHID];
__device__ float g_xg  [NNODE*NHID];
__device__ float g_fg  [NNODE*NHID];
__device__ float g_M   [HEADS*NHID*NHID];
__device__ float g_Ncat[HEADS*NHID*64];
__device__ float g_ccat[HEADS*NHID];
__device__ float g_dcat[HEADS*64];
__device__ float g_tvec[2*NNODE];
__device__ float g_sin [2*NNODE];
__device__ float g_sout[2*NNODE];
__device__ float g_inv1[2*NNODE];
__device__ int   g_ind [2*NNODE];
__device__ int   g_outd[2*NNODE];
__device__ int   g_off [2*NNODE];
__device__ int   g_cur [2*NNODE];
__device__ int   g_csr [2*EE];
__device__ unsigned g_pm[(size_t)BB*HEADS*LL*(LL/32)];   // packed mask bits (4 MB)

__constant__ int c_pat[8] = {0,0,1,1,0,0,1,1};

// ----------------------------- common GEMM param block ---------------------
struct GP {
    const float *A, *B, *bias, *res;
    float *C;
    int lda, ldb, ldc, ldres;
    int M, N, K;
    float resScale;
    int relu;
    int zDiv;
    int hmode;     // per-head graph GEMM mode: A selected by (z>>1)&1
    long long aO, aI, bO, bI, cO, cI, rO, rI, biasO;
};

// ----------------------------- tf32 helpers --------------------------------
__device__ __forceinline__ unsigned f2tf(float f) {
    unsigned u; asm("cvt.rna.tf32.f32 %0, %1;" : "=r"(u) : "f"(f)); return u;
}
__device__ __forceinline__ uint4 cvt4(float4 v) {
    uint4 r; r.x=f2tf(v.x); r.y=f2tf(v.y); r.z=f2tf(v.z); r.w=f2tf(v.w); return r;
}
__device__ __forceinline__ void ldsm4(unsigned &d0, unsigned &d1, unsigned &d2, unsigned &d3,
                                      unsigned addr) {
    asm volatile("ldmatrix.sync.aligned.m8n8.x4.shared.b16 {%0,%1,%2,%3}, [%4];"
                 : "=r"(d0), "=r"(d1), "=r"(d2), "=r"(d3) : "r"(addr));
}
__device__ __forceinline__ void mma8(float* c, const unsigned* a, const unsigned* b) {
    asm volatile(
        "mma.sync.aligned.m16n8k8.row.col.f32.tf32.tf32.f32 "
        "{%0,%1,%2,%3}, {%4,%5,%6,%7}, {%8,%9}, {%0,%1,%2,%3};"
        : "+f"(c[0]), "+f"(c[1]), "+f"(c[2]), "+f"(c[3])
        : "r"(a[0]), "r"(a[1]), "r"(a[2]), "r"(a[3]), "r"(b[0]), "r"(b[1]));
}

// ----------------------------- tf32 tensor-core GEMM -----------------------
// CTA tile 128 x BN, 8 warps, K-slice 16.
template<int BN, int WGN, bool TB>
__global__ __launch_bounds__(256) void mma_k(GP p) {
    constexpr int WGM = 8 / WGN;
    constexpr int WM  = 128 / WGM;
    constexpr int WN  = BN / WGN;
    constexpr int MF  = WM / 16;
    constexpr int NF  = WN / 8;
    constexpr int AST = 20;        // A smem row stride (words), conflict-free for ldmatrix
    constexpr int BST = BN + 8;    // B smem row stride: =8 mod 32 -> conflict-free frag LDS

    __shared__ unsigned sA[128 * AST];
    __shared__ unsigned sB[16 * BST];

    const float *A, *B; float *C;
    const float *bias = nullptr, *res = nullptr;
    if (p.hmode) {
        int hd = blockIdx.z;
        A = p.A + (((hd >> 1) & 1) ? p.aI : 0);
        B = p.B + (size_t)hd * p.bO;
        C = p.C + (size_t)hd * p.cO;
    } else {
        int zo = blockIdx.z / p.zDiv, zi = blockIdx.z % p.zDiv;
        A = p.A + zo * p.aO + zi * p.aI;
        B = p.B + zo * p.bO + zi * p.bI;
        C = p.C + zo * p.cO + zi * p.cI;
        if (p.bias) bias = p.bias + zo * p.biasO;
        if (p.res)  res  = p.res + zo * p.rO + zi * p.rI;
    }

    int tid = threadIdx.x, lane = tid & 31, warp = tid >> 5;
    int wm = warp / WGN, wn = warp % WGN;
    int m0 = blockIdx.x * 128, n0 = blockIdx.y * BN;

    int ar = tid >> 1, ak = (tid & 1) * 8;
    bool aval = (m0 + ar) < p.M;
    const float* aptr = A + (size_t)(m0 + ar) * p.lda + ak;

    const float* bptr;
    int bn_t = 0, bk_t = 0, bn4_t = 0;
    if (TB) {
        bn_t = tid >> 1; bk_t = (tid & 1) * 8;
        bptr = B + (size_t)(n0 + bn_t) * p.ldb + bk_t;
    } else if (BN == 128) {
        bk_t = tid >> 5; bn4_t = (tid & 31) * 4;
        bptr = B + (size_t)bk_t * p.ldb + n0 + bn4_t;
    } else {
        bk_t = tid >> 4; bn4_t = (tid & 15) * 4;
        bptr = B + (size_t)bk_t * p.ldb + n0 + bn4_t;
    }

    float acc[MF][NF][4];
    #pragma unroll
    for (int f = 0; f < MF; f++)
        #pragma unroll
        for (int j = 0; j < NF; j++)
            #pragma unroll
            for (int q = 0; q < 4; q++) acc[f][j][q] = 0.f;

    unsigned sAb = (unsigned)__cvta_generic_to_shared(sA);

    float4 pa0, pa1, pb0, pb1;
    pb0 = pb1 = make_float4(0.f,0.f,0.f,0.f);

    if (aval) { pa0 = *(const float4*)(aptr); pa1 = *(const float4*)(aptr + 4); }
    else      { pa0 = pa1 = make_float4(0.f,0.f,0.f,0.f); }
    if (TB)             { pb0 = *(const float4*)(bptr); pb1 = *(const float4*)(bptr + 4); }
    else if (BN == 128) { pb0 = *(const float4*)(bptr); pb1 = *(const float4*)(bptr + (size_t)8 * p.ldb); }
    else                { pb0 = *(const float4*)(bptr); }

    for (int k0 = 0; k0 < p.K; k0 += 16) {
        __syncthreads();
        *(uint4*)&sA[ar * AST + ak]     = cvt4(pa0);
        *(uint4*)&sA[ar * AST + ak + 4] = cvt4(pa1);
        if (TB) {
            sB[(bk_t + 0) * BST + bn_t] = f2tf(pb0.x);
            sB[(bk_t + 1) * BST + bn_t] = f2tf(pb0.y);
            sB[(bk_t + 2) * BST + bn_t] = f2tf(pb0.z);
            sB[(bk_t + 3) * BST + bn_t] = f2tf(pb0.w);
            sB[(bk_t + 4) * BST + bn_t] = f2tf(pb1.x);
            sB[(bk_t + 5) * BST + bn_t] = f2tf(pb1.y);
            sB[(bk_t + 6) * BST + bn_t] = f2tf(pb1.z);
            sB[(bk_t + 7) * BST + bn_t] = f2tf(pb1.w);
        } else if (BN == 128) {
            *(uint4*)&sB[bk_t * BST + bn4_t]       = cvt4(pb0);
            *(uint4*)&sB[(bk_t + 8) * BST + bn4_t] = cvt4(pb1);
        } else {
            *(uint4*)&sB[bk_t * BST + bn4_t] = cvt4(pb0);
        }
        __syncthreads();

        if (k0 + 16 < p.K) {
            if (aval) { pa0 = *(const float4*)(aptr + k0 + 16); pa1 = *(const float4*)(aptr + k0 + 20); }
            if (TB)             { pb0 = *(const float4*)(bptr + k0 + 16); pb1 = *(const float4*)(bptr + k0 + 20); }
            else if (BN == 128) { pb0 = *(const float4*)(bptr + (size_t)(k0 + 16) * p.ldb);
                                  pb1 = *(const float4*)(bptr + (size_t)(k0 + 24) * p.ldb); }
            else                { pb0 = *(const float4*)(bptr + (size_t)(k0 + 16) * p.ldb); }
        }

        #pragma unroll
        for (int kk = 0; kk < 16; kk += 8) {
            unsigned bfr[NF][2];
            #pragma unroll
            for (int j = 0; j < NF; j++) {
                int nb = wn * WN + j * 8 + (lane >> 2);
                bfr[j][0] = sB[(kk + (lane & 3)) * BST + nb];
                bfr[j][1] = sB[(kk + 4 + (lane & 3)) * BST + nb];
            }
            #pragma unroll
            for (int f = 0; f < MF; f++) {
                int mi = lane >> 3, r = lane & 7;
                int row = wm * WM + f * 16 + r + (mi & 1) * 8;
                unsigned addr = sAb + 4u * (unsigned)(row * AST + kk + (mi >> 1) * 4);
                unsigned afr[4];
                ldsm4(afr[0], afr[1], afr[2], afr[3], addr);
                #pragma unroll
                for (int j = 0; j < NF; j++) mma8(acc[f][j], afr, bfr[j]);
            }
        }
    }

    #pragma unroll
    for (int f = 0; f < MF; f++) {
        int r0 = m0 + wm * WM + f * 16 + (lane >> 2);
        int r1 = r0 + 8;
        #pragma unroll
        for (int j = 0; j < NF; j++) {
            int col = n0 + wn * WN + j * 8 + 2 * (lane & 3);
            float b0 = 0.f, b1 = 0.f;
            if (bias) { b0 = bias[col]; b1 = bias[col + 1]; }
            float v0 = acc[f][j][0] + b0, v1 = acc[f][j][1] + b1;
            float v2 = acc[f][j][2] + b0, v3 = acc[f][j][3] + b1;
            if (p.relu) {
                v0 = fmaxf(v0, 0.f); v1 = fmaxf(v1, 0.f);
                v2 = fmaxf(v2, 0.f); v3 = fmaxf(v3, 0.f);
            }
            if (r0 < p.M) {
                if (res) {
                    v0 += p.resScale * res[(size_t)r0 * p.ldres + col];
                    v1 += p.resScale * res[(size_t)r0 * p.ldres + col + 1];
                }
                *(float2*)&C[(size_t)r0 * p.ldc + col] = make_float2(v0, v1);
            }
            if (r1 < p.M) {
                if (res) {
                    v2 += p.resScale * res[(size_t)r1 * p.ldres + col];
                    v3 += p.resScale * res[(size_t)r1 * p.ldres + col + 1];
                }
                *(float2*)&C[(size_t)r1 * p.ldc + col] = make_float2(v2, v3);
            }
        }
    }
}

static void mgemm(const float* A, int lda, const float* B, int ldb, float* C, int ldc,
                  int M, int N, int K,
                  const float* bias = nullptr, const float* res = nullptr, int ldres = 0,
                  float resScale = 0.f, int relu = 0, int transB = 0,
                  int z = 1, int zDiv = 1,
                  long long aO=0, long long aI=0, long long bO=0, long long bI=0,
                  long long cO=0, long long cI=0, long long rO=0, long long rI=0,
                  long long biasO=0, int hmode = 0) {
    GP p;
    p.A=A; p.B=B; p.bias=bias; p.res=res; p.C=C;
    p.lda=lda; p.ldb=ldb; p.ldc=ldc; p.ldres=ldres;
    p.M=M; p.N=N; p.K=K; p.resScale=resScale; p.relu=relu; p.zDiv=zDiv; p.hmode=hmode;
    p.aO=aO; p.aI=aI; p.bO=bO; p.bI=bI; p.cO=cO; p.cI=cI; p.rO=rO; p.rI=rI; p.biasO=biasO;
    if (transB) {
        dim3 grid((M + 127) / 128, N / 128, z);
        mma_k<128, 4, true><<<grid, 256>>>(p);
    } else if (N % 128 == 0) {
        dim3 grid((M + 127) / 128, N / 128, z);
        mma_k<128, 4, false><<<grid, 256>>>(p);
    } else {
        dim3 grid((M + 127) / 128, N / 64, z);
        mma_k<64, 2, false><<<grid, 256>>>(p);
    }
}

// ----------------------------- fused flash attention -----------------------
// grid (L/128, B*H), 256 threads (8 warps), each warp owns 16 rows.
// smem: sQ 128x68, sK(dim-major) 64x136, sV 128x72, sP 128x132  (~170 KB)
#define SQ_ST 68
#define SK_ST 136
#define SV_ST 72
#define SP_ST 132
#define FLASH_SMEM ((128*SQ_ST + 64*SK_ST + 128*SV_ST + 128*SP_ST) * 4)

__global__ __launch_bounds__(256) void k_flash() {
    extern __shared__ unsigned sm[];
    unsigned* sQ = sm;
    unsigned* sK = sQ + 128*SQ_ST;
    unsigned* sV = sK + 64*SK_ST;
    unsigned* sP = sV + 128*SV_ST;

    int tid = threadIdx.x, lane = tid & 31, w = tid >> 5;
    int m0 = blockIdx.x * 128;
    int bh = blockIdx.y; int h = bh & 7, b = bh >> 3;
    const float* qbase = g_qkv + (size_t)(b * LL) * QKVD + h * 192;

    // ---- load Q tile (rows m0..m0+127, dims 0..63), cvt to tf32 ----
    {
        int row = tid >> 1, half = tid & 1;
        const float* src = qbase + (size_t)(m0 + row) * QKVD + half * 32;
        unsigned* dst = sQ + row * SQ_ST + half * 32;
        #pragma unroll
        for (int c = 0; c < 8; c++)
            *(uint4*)(dst + 4*c) = cvt4(*(const float4*)(src + 4*c));
    }

    float accO[8][4];
    #pragma unroll
    for (int j = 0; j < 8; j++)
        #pragma unroll
        for (int q = 0; q < 4; q++) accO[j][q] = 0.f;
    float m0r = -INFINITY, m1r = -INFINITY, l0r = 0.f, l1r = 0.f;

    unsigned sQb = (unsigned)__cvta_generic_to_shared(sQ);
    unsigned sPb = (unsigned)__cvta_generic_to_shared(sP);
    const unsigned* pmr0 = g_pm + ((size_t)bh * LL + m0 + 16*w + (lane >> 2)) * 16;
    const unsigned* pmr1 = pmr0 + 8 * 16;

    for (int kt = 0; kt < 4; kt++) {
        __syncthreads();
        // ---- load K (transposed to [dim][key]) and V ([key][dim]) ----
        {
            int key = tid >> 1, half = tid & 1;
            const float* ks = qbase + (size_t)(kt*128 + key) * QKVD + 64 + half*32;
            #pragma unroll
            for (int c = 0; c < 8; c++) {
                float4 v = *(const float4*)(ks + 4*c);
                int d = half*32 + 4*c;
                sK[(d+0)*SK_ST + key] = f2tf(v.x);
                sK[(d+1)*SK_ST + key] = f2tf(v.y);
                sK[(d+2)*SK_ST + key] = f2tf(v.z);
                sK[(d+3)*SK_ST + key] = f2tf(v.w);
            }
            const float* vs = qbase + (size_t)(kt*128 + key) * QKVD + 128 + half*32;
            unsigned* vd = sV + key * SV_ST + half*32;
            #pragma unroll
            for (int c = 0; c < 8; c++)
                *(uint4*)(vd + 4*c) = cvt4(*(const float4*)(vs + 4*c));
        }
        __syncthreads();

        // ---- S = Q K^T (16 rows per warp x 128 cols) ----
        float S[16][4];
        #pragma unroll
        for (int nt = 0; nt < 16; nt++)
            #pragma unroll
            for (int q = 0; q < 4; q++) S[nt][q] = 0.f;

        int mi = lane >> 3, rr = lane & 7;
        int arow = 16*w + rr + (mi & 1) * 8;
        #pragma unroll
        for (int kk = 0; kk < 64; kk += 8) {
            unsigned a[4];
            ldsm4(a[0], a[1], a[2], a[3],
                  sQb + 4u * (unsigned)(arow * SQ_ST + kk + (mi >> 1) * 4));
            #pragma unroll
            for (int nt = 0; nt < 16; nt++) {
                unsigned bb[2];
                int nb = nt*8 + (lane >> 2);
                bb[0] = sK[(kk     + (lane & 3)) * SK_ST + nb];
                bb[1] = sK[(kk + 4 + (lane & 3)) * SK_ST + nb];
                mma8(S[nt], a, bb);
            }
        }

        // ---- mask + scale ----
        uint4 mw0 = *(const uint4*)(pmr0 + kt*4);
        uint4 mw1 = *(const uint4*)(pmr1 + kt*4);
        unsigned q0[4] = {mw0.x, mw0.y, mw0.z, mw0.w};
        unsigned q1[4] = {mw1.x, mw1.y, mw1.z, mw1.w};
        float rm0 = -INFINITY, rm1 = -INFINITY;
        #pragma unroll
        for (int nt = 0; nt < 16; nt++) {
            int j0 = nt*8 + 2*(lane & 3), j1 = j0 + 1;
            S[nt][0] = ((q0[j0>>5] >> (j0&31)) & 1u) ? S[nt][0]*0.125f : -INFINITY;
            S[nt][1] = ((q0[j1>>5] >> (j1&31)) & 1u) ? S[nt][1]*0.125f : -INFINITY;
            S[nt][2] = ((q1[j0>>5] >> (j0&31)) & 1u) ? S[nt][2]*0.125f : -INFINITY;
            S[nt][3] = ((q1[j1>>5] >> (j1&31)) & 1u) ? S[nt][3]*0.125f : -INFINITY;
            rm0 = fmaxf(rm0, fmaxf(S[nt][0], S[nt][1]));
            rm1 = fmaxf(rm1, fmaxf(S[nt][2], S[nt][3]));
        }
        rm0 = fmaxf(rm0, __shfl_xor_sync(0xffffffffu, rm0, 1));
        rm0 = fmaxf(rm0, __shfl_xor_sync(0xffffffffu, rm0, 2));
        rm1 = fmaxf(rm1, __shfl_xor_sync(0xffffffffu, rm1, 1));
        rm1 = fmaxf(rm1, __shfl_xor_sync(0xffffffffu, rm1, 2));

        float mn0 = fmaxf(m0r, rm0), mn1 = fmaxf(m1r, rm1);
        float a0 = __expf(m0r - mn0), a1 = __expf(m1r - mn1);
        m0r = mn0; m1r = mn1;

        // ---- P = exp(S - m), row sums, stash P into sP as tf32 ----
        int prow0 = 16*w + (lane >> 2), prow1 = prow0 + 8;
        float rs0 = 0.f, rs1 = 0.f;
        #pragma unroll
        for (int nt = 0; nt < 16; nt++) {
            int j0 = nt*8 + 2*(lane & 3);
            float p00 = __expf(S[nt][0] - mn0), p01 = __expf(S[nt][1] - mn0);
            float p10 = __expf(S[nt][2] - mn1), p11 = __expf(S[nt][3] - mn1);
            rs0 += p00 + p01; rs1 += p10 + p11;
            sP[prow0*SP_ST + j0]     = f2tf(p00);
            sP[prow0*SP_ST + j0 + 1] = f2tf(p01);
            sP[prow1*SP_ST + j0]     = f2tf(p10);
            sP[prow1*SP_ST + j0 + 1] = f2tf(p11);
        }
        rs0 += __shfl_xor_sync(0xffffffffu, rs0, 1);
        rs0 += __shfl_xor_sync(0xffffffffu, rs0, 2);
        rs1 += __shfl_xor_sync(0xffffffffu, rs1, 1);
        rs1 += __shfl_xor_sync(0xffffffffu, rs1, 2);
        l0r = l0r * a0 + rs0;
        l1r = l1r * a1 + rs1;

        #pragma unroll
        for (int j = 0; j < 8; j++) {
            accO[j][0] *= a0; accO[j][1] *= a0;
            accO[j][2] *= a1; accO[j][3] *= a1;
        }
        __syncwarp();

        // ---- O += P @ V ----
        #pragma unroll
        for (int kk = 0; kk < 128; kk += 8) {
            unsigned a[4];
            ldsm4(a[0], a[1], a[2], a[3],
                  sPb + 4u * (unsigned)(arow * SP_ST + kk + (mi >> 1) * 4));
            #pragma unroll
            for (int nt = 0; nt < 8; nt++) {
                unsigned bb[2];
                int nb = nt*8 + (lane >> 2);
                bb[0] = sV[(kk     + (lane & 3)) * SV_ST + nb];
                bb[1] = sV[(kk + 4 + (lane & 3)) * SV_ST + nb];
                mma8(accO[nt], a, bb);
            }
        }
    }

    // ---- epilogue: O /= l, write to g_o[b, i, h*64 + d] ----
    float inv0 = 1.f / l0r, inv1 = 1.f / l1r;
    int r0 = m0 + 16*w + (lane >> 2), r1 = r0 + 8;
    float* o0 = g_o + (size_t)(b*LL + r0) * NHID + h*64;
    float* o1 = g_o + (size_t)(b*LL + r1) * NHID + h*64;
    #pragma unroll
    for (int nt = 0; nt < 8; nt++) {
        int col = nt*8 + 2*(lane & 3);
        *(float2*)(o0 + col) = make_float2(accO[nt][0]*inv0, accO[nt][1]*inv0);
        *(float2*)(o1 + col) = make_float2(accO[nt][2]*inv1, accO[nt][3]*inv1);
    }
}

// pack mask (int32 bool, layout [b][i][h][j]) -> bits [b][h][i][j/32]
__global__ void k_packmask(const int* __restrict__ mask) {
    int row = blockIdx.x * 8 + (threadIdx.x >> 5);   // (b*512 + i)*8 + h
    int lane = threadIdx.x & 31;
    const int* mr = mask + (size_t)row * LL;
    int b_i = row >> 3, h = row & 7;
    int b = b_i >> 9, i = b_i & 511;
    unsigned* out = g_pm + (((size_t)(b*HEADS + h) * LL + i) << 4);
    #pragma unroll
    for (int wd = 0; wd < 16; wd++) {
        unsigned bits = __ballot_sync(0xffffffffu, mr[wd*32 + lane] != 0);
        if (lane == 0) out[wd] = bits;
    }
}

// ----------------------------- small FFMA GEMM (tiny M=1 cases) ------------
__global__ void gemm1_k(GP p) {
    int zo = blockIdx.z;
    const float* A = p.A + zo * p.aO;
    const float* B = p.B + zo * p.bO;
    float* C = p.C + zo * p.cO;
    const float* bias = p.bias ? p.bias + zo * p.biasO : nullptr;
    int n = blockIdx.x * 64 + threadIdx.x;
    if (n >= p.N) return;
    float s = 0.f;
    for (int k = 0; k < p.K; k++) s += A[k] * B[(size_t)k * p.ldb + n];
    if (bias) s += bias[n];
    C[n] = s;
}

// ----------------------------- small kernels -------------------------------
__global__ void k_embed(const float* __restrict__ emb, const float* __restrict__ pos,
                        const int* __restrict__ idxs) {
    int tok = blockIdx.x;
    int b = tok >> 9, s = tok & 511;
    int id = (s == 0) ? 0 : idxs[b*SS + s - 1];
    const float4* e  = (const float4*)(emb + (size_t)id * NHID);
    const float4* pr = (const float4*)(pos + (size_t)s  * NHID);
    float4* hr = (float4*)(g_h + (size_t)tok * NHID);
    int t = threadIdx.x;
    float4 a = e[t], c = pr[t];
    hr[t] = make_float4(a.x+c.x, a.y+c.y, a.z+c.z, a.w+c.w);
}

__global__ void k_ln_add(float* __restrict__ out, const float* __restrict__ inp,
                         const float* __restrict__ base, int hgMap,
                         const float* __restrict__ gw, const float* __restrict__ bw) {
    int n = blockIdx.x;
    const float* xr = inp + (size_t)n * NHID;
    size_t brow;
    if (hgMap) { int b = n / SS, s = n % SS; brow = ((size_t)(b*LL + s + 1)) * NHID; }
    else brow = (size_t)n * NHID;
    int t = threadIdx.x;  // 128
    float x[4];
    #pragma unroll
    for (int i = 0; i < 4; i++) x[i] = xr[t + i*128];
    __shared__ float red[128];
    red[t] = x[0]+x[1]+x[2]+x[3]; __syncthreads();
    for (int s = 64; s > 0; s >>= 1) { if (t < s) red[t] += red[t+s]; __syncthreads(); }
    float mu = red[0] * (1.f/512.f); __syncthreads();
    float d[4], vs = 0.f;
    #pragma unroll
    for (int i = 0; i < 4; i++) { d[i] = x[i] - mu; vs += d[i]*d[i]; }
    red[t] = vs; __syncthreads();
    for (int s = 64; s > 0; s >>= 1) { if (t < s) red[t] += red[t+s]; __syncthreads(); }
    float inv = rsqrtf(red[0] * (1.f/512.f) + 1e-5f);
    #pragma unroll
    for (int i = 0; i < 4; i++) {
        int c = t + i*128;
        out[(size_t)n*NHID + c] = base[brow + c] + d[i]*inv*gw[c] + bw[c];
    }
}

__global__ void k_zg(float* __restrict__ dout) {
    int b = blockIdx.x; int t = threadIdx.x;
    #pragma unroll
    for (int i = 0; i < 4; i++) {
        int c = t + i*128;
        dout[(size_t)NNODE*NHID + b*NHID + c] = g_h[((size_t)b*LL) * NHID + c];
    }
}

__global__ void k_copyxf() {
    int n = blockIdx.x;
    int b = n / SS, s = n % SS;
    const float4* src = (const float4*)(g_h + ((size_t)(b*LL + s + 1)) * NHID);
    float4* dst = (float4*)(g_xf + (size_t)n * NHID);
    dst[threadIdx.x] = src[threadIdx.x];
}

__global__ void k_zero_ints() {
    int i = blockIdx.x*blockDim.x + threadIdx.x;
    if (i < 2*NNODE) { g_ind[i] = 0; g_outd[i] = 0; g_cur[i] = 0; }
}

__global__ void k_count(const int* __restrict__ src, const int* __restrict__ dst, int gi) {
    int e = blockIdx.x*blockDim.x + threadIdx.x;
    if (e < EE) {
        atomicAdd(&g_ind [gi*NNODE + dst[e]], 1);
        atomicAdd(&g_outd[gi*NNODE + src[e]], 1);
    }
}

__global__ void k_scan(int gi) {
    __shared__ int sh[1024];
    int t = threadIdx.x;
    int base = gi * NNODE;
    int loc[8]; int sum = 0;
    #pragma unroll
    for (int i = 0; i < 8; i++) {
        int idx = t*8 + i;
        int v = (idx < NNODE) ? g_ind[base + idx] : 0;
        loc[i] = sum; sum += v;
    }
    sh[t] = sum; __syncthreads();
    for (int d = 1; d < 1024; d <<= 1) {
        int v = (t >= d) ? sh[t-d] : 0; __syncthreads();
        sh[t] += v; __syncthreads();
    }
    int pre = (t > 0) ? sh[t-1] : 0;
    #pragma unroll
    for (int i = 0; i < 8; i++) {
        int idx = t*8 + i;
        if (idx < NNODE) g_off[base + idx] = pre + loc[i];
    }
}

__global__ void k_scatter(const int* __restrict__ src, const int* __restrict__ dst, int gi) {
    int e = blockIdx.x*blockDim.x + threadIdx.x;
    if (e < EE) {
        int d = dst[e];
        int p = g_off[gi*NNODE + d] + atomicAdd(&g_cur[gi*NNODE + d], 1);
        g_csr[gi*EE + p] = src[e];
    }
}

__global__ void k_scales() {
    int i = blockIdx.x*blockDim.x + threadIdx.x;
    if (i < 2*NNODE) {
        float in = (float)g_ind[i], od = (float)g_outd[i];
        g_sin [i] = rsqrtf(fmaxf(in, 1.f));
        g_sout[i] = rsqrtf(fmaxf(od, 1.f));
        g_inv1[i] = 1.f / (in + 1.f);
    }
}

__global__ void k_prop_sage(const float* __restrict__ x, float* __restrict__ out, int gi) {
    int wid = blockIdx.x * (blockDim.x >> 5) + (threadIdx.x >> 5);
    if (wid >= NNODE) return;
    int lane = threadIdx.x & 31;
    const float4* xr = (const float4*)(x + (size_t)wid * NHID);
    float4 a0 = xr[lane], a1 = xr[lane+32], a2 = xr[lane+64], a3 = xr[lane+96];
    int s = g_off[gi*NNODE + wid], e = s + g_ind[gi*NNODE + wid];
    const int* csr = g_csr + gi*EE;
    for (int j = s; j < e; j++) {
        int sn = csr[j];
        const float4* sr = (const float4*)(x + (size_t)sn * NHID);
        float4 v;
        v = sr[lane];    a0.x+=v.x; a0.y+=v.y; a0.z+=v.z; a0.w+=v.w;
        v = sr[lane+32]; a1.x+=v.x; a1.y+=v.y; a1.z+=v.z; a1.w+=v.w;
        v = sr[lane+64]; a2.x+=v.x; a2.y+=v.y; a2.z+=v.z; a2.w+=v.w;
        v = sr[lane+96]; a3.x+=v.x; a3.y+=v.y; a3.z+=v.z; a3.w+=v.w;
    }
    float sc = g_inv1[gi*NNODE + wid];
    float4* o = (float4*)(out + (size_t)wid * NHID);
    a0.x*=sc; a0.y*=sc; a0.z*=sc; a0.w*=sc; o[lane]    = a0;
    a1.x*=sc; a1.y*=sc; a1.z*=sc; a1.w*=sc; o[lane+32] = a1;
    a2.x*=sc; a2.y*=sc; a2.z*=sc; a2.w*=sc; o[lane+64] = a2;
    a3.x*=sc; a3.y*=sc; a3.z*=sc; a3.w*=sc; o[lane+96] = a3;
}

__global__ void k_prop_gc(const float* __restrict__ q, float* __restrict__ outT, int gi) {
    int wid = blockIdx.x * (blockDim.x >> 5) + (threadIdx.x >> 5);
    if (wid >= NNODE) return;
    int lane = threadIdx.x & 31;
    float4 a0 = make_float4(0,0,0,0), a1 = a0, a2 = a0, a3 = a0;
    float ts = 0.f;
    int s = g_off[gi*NNODE + wid], e = s + g_ind[gi*NNODE + wid];
    const int* csr = g_csr + gi*EE;
    for (int j = s; j < e; j++) {
        int sn = csr[j];
        float so = g_sout[gi*NNODE + sn];
        ts += so;
        const float4* sr = (const float4*)(q + (size_t)sn * NHID);
        float4 v;
        v = sr[lane];    a0.x+=v.x*so; a0.y+=v.y*so; a0.z+=v.z*so; a0.w+=v.w*so;
        v = sr[lane+32]; a1.x+=v.x*so; a1.y+=v.y*so; a1.z+=v.z*so; a1.w+=v.w*so;
        v = sr[lane+64]; a2.x+=v.x*so; a2.y+=v.y*so; a2.z+=v.z*so; a2.w+=v.w*so;
        v = sr[lane+96]; a3.x+=v.x*so; a3.y+=v.y*so; a3.z+=v.z*so; a3.w+=v.w*so;
    }
    float4* o = (float4*)(outT + (size_t)wid * NHID);
    o[lane] = a0; o[lane+32] = a1; o[lane+64] = a2; o[lane+96] = a3;
    if (lane == 0) g_tvec[gi*NNODE + wid] = ts;
}

__global__ void k_xcepi(const float* __restrict__ gc3b) {
    int n = blockIdx.x; int c = threadIdx.x;
    int g = c_pat[c >> 6];
    float si = g_sin[g*NNODE + n], tv = g_tvec[g*NNODE + n];
    size_t idx = (size_t)n*NHID + c;
    g_xc[idx] = si * g_xc[idx] + si * tv * g_dcat[c] + gc3b[c];
}

// ----------------------------- host orchestration --------------------------
#define SYM(name, var) { void* _p; cudaGetSymbolAddress(&_p, name); var = (float*)_p; }

extern "C" void kernel_launch(void* const* d_in, const int* in_sizes, int n_in,
                              void* d_out, int out_size) {
    const float* in_embed  = (const float*)d_in[0];
    const float* pos_embed = (const float*)d_in[1];
    const float* qkv_w     = (const float*)d_in[2];
    const float* qkv_b     = (const float*)d_in[3];
    const float* attn_w    = (const float*)d_in[4];
    const float* attn_b    = (const float*)d_in[5];
    const float* ff1_w     = (const float*)d_in[6];
    const float* ff1_b     = (const float*)d_in[7];
    const float* ff2_w     = (const float*)d_in[8];
    const float* ff2_b     = (const float*)d_in[9];
    const float* sage1_w   = (const float*)d_in[10];
    const float* sage1_b   = (const float*)d_in[11];
    const float* sage2_w   = (const float*)d_in[12];
    const float* sage2_b   = (const float*)d_in[13];
    const float* gc3_w     = (const float*)d_in[14];
    const float* gc3_b     = (const float*)d_in[15];
    const float* gff1_w    = (const float*)d_in[16];
    const float* gff1_b    = (const float*)d_in[17];
    const float* gff2_w    = (const float*)d_in[18];
    const float* gff2_b    = (const float*)d_in[19];
    const float* ln_g      = (const float*)d_in[20];
    const float* ln_b      = (const float*)d_in[21];
    const int*   in_idxs   = (const int*)d_in[22];
    const int*   mask      = (const int*)d_in[23];   // bool marshalled as int32
    const int*   gt_src    = (const int*)d_in[24];
    const int*   gt_dst    = (const int*)d_in[25];
    const int*   at_src    = (const int*)d_in[26];
    const int*   at_dst    = (const int*)d_in[27];

    float *h, *qkv, *o, *x, *ff, *xf, *P, *Q, *T, *xc, *xg, *fg, *Mb, *Nc, *cc, *dc;
    SYM(g_h, h); SYM(g_qkv, qkv); SYM(g_o, o); SYM(g_x, x); SYM(g_ff, ff);
    SYM(g_xf, xf); SYM(g_P, P); SYM(g_Q, Q); SYM(g_T, T); SYM(g_xc, xc); SYM(g_xg, xg);
    SYM(g_fg, fg); SYM(g_M, Mb); SYM(g_Ncat, Nc); SYM(g_ccat, cc); SYM(g_dcat, dc);

    static int smemSet = 0;
    if (!smemSet) {
        cudaFuncSetAttribute(k_flash, cudaFuncAttributeMaxDynamicSharedMemorySize, FLASH_SMEM);
        smemSet = 1;
    }

    // ---- embedding + mask packing ----
    k_embed<<<NTOK, 128>>>(in_embed, pos_embed, in_idxs);
    k_packmask<<<BB*LL*HEADS/8, 256>>>(mask);

    // ---- transformer layers ----
    for (int l = 0; l < 4; l++) {
        // qkv = h @ W + b
        mgemm(h, NHID, qkv_w + (size_t)l*NHID*QKVD, QKVD, qkv, QKVD,
              NTOK, QKVD, NHID, qkv_b + l*QKVD);
        // fused attention: o = softmax(mask, QK^T/8) @ V
        k_flash<<<dim3(LL/128, BB*HEADS), 256, FLASH_SMEM>>>();
        // x = 2h + (o @ Wout + b)
        mgemm(o, NHID, attn_w + (size_t)l*NHID*NHID, NHID, x, NHID,
              NTOK, NHID, NHID, attn_b + l*NHID, h, NHID, 2.0f);
        // ff = relu(x @ W1 + b1)
        mgemm(x, NHID, ff1_w + (size_t)l*NHID*FFD, FFD, ff, FFD,
              NTOK, FFD, NHID, ff1_b + l*FFD, nullptr, 0, 0.f, /*relu=*/1);
        // h = x + (ff @ W2 + b2)
        mgemm(ff, FFD, ff2_w + (size_t)l*FFD*NHID, NHID, h, NHID,
              NTOK, NHID, FFD, ff2_b + l*NHID, x, NHID, 1.0f);
    }

    // ---- graph preprocessing ----
    k_zero_ints<<<(2*NNODE + 255)/256, 256>>>();
    k_count<<<EE/256, 256>>>(gt_src, gt_dst, 0);
    k_count<<<EE/256, 256>>>(at_src, at_dst, 1);
    k_scan<<<1, 1024>>>(0);
    k_scan<<<1, 1024>>>(1);
    k_scatter<<<EE/256, 256>>>(gt_src, gt_dst, 0);
    k_scatter<<<EE/256, 256>>>(at_src, at_dst, 1);
    k_scales<<<(2*NNODE + 255)/256, 256>>>();
    k_copyxf<<<NNODE, 128>>>();

    // ---- propagations (3 per graph) ----
    int propBlocks = (NNODE + 7) / 8;
    for (int g = 0; g < 2; g++) {
        k_prop_sage<<<propBlocks, 256>>>(xf, P, g);
        k_prop_sage<<<propBlocks, 256>>>(P,  Q, g);
        k_prop_gc  <<<propBlocks, 256>>>(Q,  T + (size_t)g*NNODE*NHID, g);
    }

    // ---- collapse per-head weights: M_i = W1 W2, N_i = M_i W3, c_i, d_i ----
    mgemm(sage1_w, NHID, sage2_w, NHID, Mb, NHID, NHID, NHID, NHID,
          nullptr, nullptr, 0, 0.f, 0, 0, HEADS, 1,
          (long long)NHID*NHID, 0, (long long)NHID*NHID, 0, (long long)NHID*NHID, 0);
    mgemm(Mb, NHID, gc3_w, 64, Nc, 64, NHID, 64, NHID,
          nullptr, nullptr, 0, 0.f, 0, 0, HEADS, 1,
          (long long)NHID*NHID, 0, (long long)NHID*64, 0, (long long)NHID*64, 0);
    {
        GP p; p.A=sage1_b; p.B=sage2_w; p.bias=sage2_b; p.res=nullptr; p.C=cc;
        p.lda=NHID; p.ldb=NHID; p.ldc=NHID; p.ldres=0;
        p.M=1; p.N=NHID; p.K=NHID; p.resScale=0; p.relu=0; p.zDiv=1; p.hmode=0;
        p.aO=NHID; p.bO=(long long)NHID*NHID; p.cO=NHID; p.biasO=NHID;
        p.aI=p.bI=p.cI=p.rO=p.rI=0;
        gemm1_k<<<dim3((NHID+63)/64,1,HEADS), 64>>>(p);
    }
    {
        GP p; p.A=cc; p.B=gc3_w; p.bias=nullptr; p.res=nullptr; p.C=dc;
        p.lda=NHID; p.ldb=64; p.ldc=64; p.ldres=0;
        p.M=1; p.N=64; p.K=NHID; p.resScale=0; p.relu=0; p.zDiv=1; p.hmode=0;
        p.aO=NHID; p.bO=(long long)NHID*64; p.cO=64; p.biasO=0;
        p.aI=p.bI=p.cI=p.rO=p.rI=0;
        gemm1_k<<<dim3(1,1,HEADS), 64>>>(p);
    }

    // ---- xc per head: one launch, A = T[(z>>1)&1], via hmode ----
    mgemm(T, NHID, Nc, 64, xc, NHID,
          NNODE, 64, NHID, nullptr, nullptr, 0, 0.f, 0, 0,
          HEADS, 1,
          0, (long long)NNODE*NHID,
          (long long)NHID*64, 0,
          64, 0, 0, 0, 0, /*hmode=*/1);
    k_xcepi<<<NNODE, 512>>>(gc3_b);

    // ---- final: x = hg + LN(xc); ff = relu(x W1+b) W2 + b; zbar = x + LN(ff) ----
    k_ln_add<<<NNODE, 128>>>(xg, xc, h, /*hgMap=*/1, ln_g, ln_b);
    mgemm(xg, NHID, gff1_w, NHID, fg, NHID, NNODE, NHID, NHID, gff1_b,
          nullptr, 0, 0.f, /*relu=*/1);
    mgemm(fg, NHID, gff2_w, NHID, xc, NHID, NNODE, NHID, NHID, gff2_b);
    k_ln_add<<<NNODE, 128>>>((float*)d_out, xc, xg, /*hgMap=*/0, ln_g, ln_b);

    // ---- zg ----
    if (out_size >= NNODE*NHID + BB*NHID)
        k_zg<<<BB, 128>>>((float*)d_out);
}

// round 5
// speedup vs baseline: 2.9646x; 1.0294x over previous
#include <cuda_runtime.h>
#include <math.h>
#include <stdint.h>

#define NHID   512
#define HEADS  8
#define NKD    64
#define BB     16
#define SS     511
#define LL     512
#define NNODE  8176      // BB*SS
#define NTOK   8192      // BB*LL
#define EE     131072
#define QKVD   1536
#define FFD    2048

// ----------------------------- scratch (device globals; no allocation) -----
__device__ float g_h   [NTOK*NHID];
__device__ float g_qkv [NTOK*QKVD];
__device__ float g_o   [NTOK*NHID];
__device__ float g_x   [NTOK*NHID];
__device__ float g_ff  [NTOK*FFD];
__device__ float g_xf  [NNODE*NHID];
__device__ float g_P   [NNODE*NHID];
__device__ float g_Q   [NNODE*NHID];
__device__ float g_T   [2*NNODE*NHID];
__device__ float g_xc  [NNODE*NHID];
__device__ float g_xg  [NNODE*NHID];
__device__ float g_fg  [NNODE*NHID];
__device__ float g_M   [HEADS*NHID*NHID];
__device__ float g_Ncat[HEADS*NHID*64];
__device__ float g_ccat[HEADS*NHID];
__device__ float g_dcat[HEADS*64];
__device__ float g_tvec[2*NNODE];
__device__ float g_sin [2*NNODE];
__device__ float g_sout[2*NNODE];
__device__ float g_inv1[2*NNODE];
__device__ int   g_ind [2*NNODE];
__device__ int   g_outd[2*NNODE];
__device__ int   g_off [2*NNODE];
__device__ int   g_cur [2*NNODE];
__device__ int   g_csr [2*EE];
__device__ unsigned g_pm[(size_t)BB*HEADS*LL*(LL/32)];   // packed mask bits (4 MB)

__constant__ int c_pat[8] = {0,0,1,1,0,0,1,1};

// ----------------------------- common GEMM param block ---------------------
struct GP {
    const float *A, *B, *bias, *res;
    float *C;
    int lda, ldb, ldc, ldres;
    int M, N, K;
    float resScale;
    int relu;
    int zDiv;
    int hmode;     // per-head graph GEMM mode: A selected by (z>>1)&1
    long long aO, aI, bO, bI, cO, cI, rO, rI, biasO;
};

// ----------------------------- tf32 helpers --------------------------------
__device__ __forceinline__ unsigned f2tf(float f) {
    unsigned u; asm("cvt.rna.tf32.f32 %0, %1;" : "=r"(u) : "f"(f)); return u;
}
__device__ __forceinline__ uint4 cvt4(float4 v) {
    uint4 r; r.x=f2tf(v.x); r.y=f2tf(v.y); r.z=f2tf(v.z); r.w=f2tf(v.w); return r;
}
__device__ __forceinline__ void ldsm4(unsigned &d0, unsigned &d1, unsigned &d2, unsigned &d3,
                                      unsigned addr) {
    asm volatile("ldmatrix.sync.aligned.m8n8.x4.shared.b16 {%0,%1,%2,%3}, [%4];"
                 : "=r"(d0), "=r"(d1), "=r"(d2), "=r"(d3) : "r"(addr));
}
__device__ __forceinline__ void mma8(float* c, const unsigned* a, const unsigned* b) {
    asm volatile(
        "mma.sync.aligned.m16n8k8.row.col.f32.tf32.tf32.f32 "
        "{%0,%1,%2,%3}, {%4,%5,%6,%7}, {%8,%9}, {%0,%1,%2,%3};"
        : "+f"(c[0]), "+f"(c[1]), "+f"(c[2]), "+f"(c[3])
        : "r"(a[0]), "r"(a[1]), "r"(a[2]), "r"(a[3]), "r"(b[0]), "r"(b[1]));
}

// ----------------------------- tf32 tensor-core GEMM -----------------------
// CTA tile 128 x BN, 8 warps, K-slice 16.
template<int BN, int WGN, bool TB>
__global__ __launch_bounds__(256) void mma_k(GP p) {
    constexpr int WGM = 8 / WGN;
    constexpr int WM  = 128 / WGM;
    constexpr int WN  = BN / WGN;
    constexpr int MF  = WM / 16;
    constexpr int NF  = WN / 8;
    constexpr int AST = 20;        // A smem row stride (words), conflict-free for ldmatrix
    constexpr int BST = BN + 8;    // B smem row stride: =8 mod 32 -> conflict-free frag LDS

    __shared__ unsigned sA[128 * AST];
    __shared__ unsigned sB[16 * BST];

    const float *A, *B; float *C;
    const float *bias = nullptr, *res = nullptr;
    if (p.hmode) {
        int hd = blockIdx.z;
        A = p.A + (((hd >> 1) & 1) ? p.aI : 0);
        B = p.B + (size_t)hd * p.bO;
        C = p.C + (size_t)hd * p.cO;
    } else {
        int zo = blockIdx.z / p.zDiv, zi = blockIdx.z % p.zDiv;
        A = p.A + zo * p.aO + zi * p.aI;
        B = p.B + zo * p.bO + zi * p.bI;
        C = p.C + zo * p.cO + zi * p.cI;
        if (p.bias) bias = p.bias + zo * p.biasO;
        if (p.res)  res  = p.res + zo * p.rO + zi * p.rI;
    }

    int tid = threadIdx.x, lane = tid & 31, warp = tid >> 5;
    int wm = warp / WGN, wn = warp % WGN;
    int m0 = blockIdx.x * 128, n0 = blockIdx.y * BN;

    int ar = tid >> 1, ak = (tid & 1) * 8;
    bool aval = (m0 + ar) < p.M;
    const float* aptr = A + (size_t)(m0 + ar) * p.lda + ak;

    const float* bptr;
    int bn_t = 0, bk_t = 0, bn4_t = 0;
    if (TB) {
        bn_t = tid >> 1; bk_t = (tid & 1) * 8;
        bptr = B + (size_t)(n0 + bn_t) * p.ldb + bk_t;
    } else if (BN == 128) {
        bk_t = tid >> 5; bn4_t = (tid & 31) * 4;
        bptr = B + (size_t)bk_t * p.ldb + n0 + bn4_t;
    } else {
        bk_t = tid >> 4; bn4_t = (tid & 15) * 4;
        bptr = B + (size_t)bk_t * p.ldb + n0 + bn4_t;
    }

    float acc[MF][NF][4];
    #pragma unroll
    for (int f = 0; f < MF; f++)
        #pragma unroll
        for (int j = 0; j < NF; j++)
            #pragma unroll
            for (int q = 0; q < 4; q++) acc[f][j][q] = 0.f;

    unsigned sAb = (unsigned)__cvta_generic_to_shared(sA);

    float4 pa0, pa1, pb0, pb1;
    pb0 = pb1 = make_float4(0.f,0.f,0.f,0.f);

    if (aval) { pa0 = *(const float4*)(aptr); pa1 = *(const float4*)(aptr + 4); }
    else      { pa0 = pa1 = make_float4(0.f,0.f,0.f,0.f); }
    if (TB)             { pb0 = *(const float4*)(bptr); pb1 = *(const float4*)(bptr + 4); }
    else if (BN == 128) { pb0 = *(const float4*)(bptr); pb1 = *(const float4*)(bptr + (size_t)8 * p.ldb); }
    else                { pb0 = *(const float4*)(bptr); }

    for (int k0 = 0; k0 < p.K; k0 += 16) {
        __syncthreads();
        *(uint4*)&sA[ar * AST + ak]     = cvt4(pa0);
        *(uint4*)&sA[ar * AST + ak + 4] = cvt4(pa1);
        if (TB) {
            sB[(bk_t + 0) * BST + bn_t] = f2tf(pb0.x);
            sB[(bk_t + 1) * BST + bn_t] = f2tf(pb0.y);
            sB[(bk_t + 2) * BST + bn_t] = f2tf(pb0.z);
            sB[(bk_t + 3) * BST + bn_t] = f2tf(pb0.w);
            sB[(bk_t + 4) * BST + bn_t] = f2tf(pb1.x);
            sB[(bk_t + 5) * BST + bn_t] = f2tf(pb1.y);
            sB[(bk_t + 6) * BST + bn_t] = f2tf(pb1.z);
            sB[(bk_t + 7) * BST + bn_t] = f2tf(pb1.w);
        } else if (BN == 128) {
            *(uint4*)&sB[bk_t * BST + bn4_t]       = cvt4(pb0);
            *(uint4*)&sB[(bk_t + 8) * BST + bn4_t] = cvt4(pb1);
        } else {
            *(uint4*)&sB[bk_t * BST + bn4_t] = cvt4(pb0);
        }
        __syncthreads();

        if (k0 + 16 < p.K) {
            if (aval) { pa0 = *(const float4*)(aptr + k0 + 16); pa1 = *(const float4*)(aptr + k0 + 20); }
            if (TB)             { pb0 = *(const float4*)(bptr + k0 + 16); pb1 = *(const float4*)(bptr + k0 + 20); }
            else if (BN == 128) { pb0 = *(const float4*)(bptr + (size_t)(k0 + 16) * p.ldb);
                                  pb1 = *(const float4*)(bptr + (size_t)(k0 + 24) * p.ldb); }
            else                { pb0 = *(const float4*)(bptr + (size_t)(k0 + 16) * p.ldb); }
        }

        #pragma unroll
        for (int kk = 0; kk < 16; kk += 8) {
            unsigned bfr[NF][2];
            #pragma unroll
            for (int j = 0; j < NF; j++) {
                int nb = wn * WN + j * 8 + (lane >> 2);
                bfr[j][0] = sB[(kk + (lane & 3)) * BST + nb];
                bfr[j][1] = sB[(kk + 4 + (lane & 3)) * BST + nb];
            }
            #pragma unroll
            for (int f = 0; f < MF; f++) {
                int mi = lane >> 3, r = lane & 7;
                int row = wm * WM + f * 16 + r + (mi & 1) * 8;
                unsigned addr = sAb + 4u * (unsigned)(row * AST + kk + (mi >> 1) * 4);
                unsigned afr[4];
                ldsm4(afr[0], afr[1], afr[2], afr[3], addr);
                #pragma unroll
                for (int j = 0; j < NF; j++) mma8(acc[f][j], afr, bfr[j]);
            }
        }
    }

    #pragma unroll
    for (int f = 0; f < MF; f++) {
        int r0 = m0 + wm * WM + f * 16 + (lane >> 2);
        int r1 = r0 + 8;
        #pragma unroll
        for (int j = 0; j < NF; j++) {
            int col = n0 + wn * WN + j * 8 + 2 * (lane & 3);
            float b0 = 0.f, b1 = 0.f;
            if (bias) { b0 = bias[col]; b1 = bias[col + 1]; }
            float v0 = acc[f][j][0] + b0, v1 = acc[f][j][1] + b1;
            float v2 = acc[f][j][2] + b0, v3 = acc[f][j][3] + b1;
            if (p.relu) {
                v0 = fmaxf(v0, 0.f); v1 = fmaxf(v1, 0.f);
                v2 = fmaxf(v2, 0.f); v3 = fmaxf(v3, 0.f);
            }
            if (r0 < p.M) {
                if (res) {
                    v0 += p.resScale * res[(size_t)r0 * p.ldres + col];
                    v1 += p.resScale * res[(size_t)r0 * p.ldres + col + 1];
                }
                *(float2*)&C[(size_t)r0 * p.ldc + col] = make_float2(v0, v1);
            }
            if (r1 < p.M) {
                if (res) {
                    v2 += p.resScale * res[(size_t)r1 * p.ldres + col];
                    v3 += p.resScale * res[(size_t)r1 * p.ldres + col + 1];
                }
                *(float2*)&C[(size_t)r1 * p.ldc + col] = make_float2(v2, v3);
            }
        }
    }
}

static void mgemm(const float* A, int lda, const float* B, int ldb, float* C, int ldc,
                  int M, int N, int K,
                  const float* bias = nullptr, const float* res = nullptr, int ldres = 0,
                  float resScale = 0.f, int relu = 0, int transB = 0,
                  int z = 1, int zDiv = 1,
                  long long aO=0, long long aI=0, long long bO=0, long long bI=0,
                  long long cO=0, long long cI=0, long long rO=0, long long rI=0,
                  long long biasO=0, int hmode = 0) {
    GP p;
    p.A=A; p.B=B; p.bias=bias; p.res=res; p.C=C;
    p.lda=lda; p.ldb=ldb; p.ldc=ldc; p.ldres=ldres;
    p.M=M; p.N=N; p.K=K; p.resScale=resScale; p.relu=relu; p.zDiv=zDiv; p.hmode=hmode;
    p.aO=aO; p.aI=aI; p.bO=bO; p.bI=bI; p.cO=cO; p.cI=cI; p.rO=rO; p.rI=rI; p.biasO=biasO;
    if (transB) {
        dim3 grid((M + 127) / 128, N / 128, z);
        mma_k<128, 4, true><<<grid, 256>>>(p);
    } else if (N % 128 == 0) {
        dim3 grid((M + 127) / 128, N / 128, z);
        mma_k<128, 4, false><<<grid, 256>>>(p);
    } else {
        dim3 grid((M + 127) / 128, N / 64, z);
        mma_k<64, 2, false><<<grid, 256>>>(p);
    }
}

// ----------------------------- fused flash attention v2 --------------------
// grid (L/128, B*H), 256 threads (8 warps), warp owns 16 Q rows.
// Q is register-resident (staged once through sP); K-tiles of 64 keys.
// smem: sK 64x72 (dim-major), sV 64x72, sP 128x68  => 70 KB, 2 CTAs/SM.
#define KT     64
#define SKST   72
#define SVST   72
#define SPST   68
#define FLASH_SMEM ((64*SKST + 64*SVST + 128*SPST) * 4)

__global__ __launch_bounds__(256, 2) void k_flash() {
    extern __shared__ unsigned sm[];
    unsigned* sK = sm;
    unsigned* sV = sK + 64*SKST;
    unsigned* sP = sV + 64*SVST;

    int tid = threadIdx.x, lane = tid & 31, w = tid >> 5;
    int m0 = blockIdx.x * 128;
    int bh = blockIdx.y; int h = bh & 7, b = bh >> 3;
    const float* qbase = g_qkv + (size_t)(b * LL) * QKVD + h * 192;

    unsigned sPb = (unsigned)__cvta_generic_to_shared(sP);
    int mi = lane >> 3, rr = lane & 7;
    int arow = 16*w + rr + (mi & 1) * 8;

    // ---- stage Q tile through sP, then pull fragments into registers ----
    {
        int row = tid >> 1, half = tid & 1;
        const float* src = qbase + (size_t)(m0 + row) * QKVD + half * 32;
        unsigned* dst = sP + row * SPST + half * 32;
        #pragma unroll
        for (int c = 0; c < 8; c++)
            *(uint4*)(dst + 4*c) = cvt4(*(const float4*)(src + 4*c));
    }
    __syncthreads();
    unsigned qf[8][4];
    #pragma unroll
    for (int kc = 0; kc < 8; kc++)
        ldsm4(qf[kc][0], qf[kc][1], qf[kc][2], qf[kc][3],
              sPb + 4u * (unsigned)(arow * SPST + kc*8 + (mi >> 1) * 4));
    __syncthreads();   // all warps done reading Q before sP is reused for P

    float accO[8][4];
    #pragma unroll
    for (int j = 0; j < 8; j++)
        #pragma unroll
        for (int q = 0; q < 4; q++) accO[j][q] = 0.f;
    float m0r = -INFINITY, m1r = -INFINITY, l0r = 0.f, l1r = 0.f;

    const unsigned* pmr0 = g_pm + ((size_t)bh * LL + m0 + 16*w + (lane >> 2)) * 16;
    const unsigned* pmr1 = pmr0 + 8 * 16;

    for (int kt = 0; kt < 8; kt++) {
        __syncthreads();   // previous tile's sK/sV reads complete
        // ---- load K (transposed [dim][key]) and V ([key][dim]), 64 keys ----
        {
            int key = tid >> 2, quarter = tid & 3;
            const float* ks = qbase + (size_t)(kt*KT + key) * QKVD + 64 + quarter*16;
            #pragma unroll
            for (int c = 0; c < 4; c++) {
                float4 v = *(const float4*)(ks + 4*c);
                int d = quarter*16 + 4*c;
                sK[(d+0)*SKST + key] = f2tf(v.x);
                sK[(d+1)*SKST + key] = f2tf(v.y);
                sK[(d+2)*SKST + key] = f2tf(v.z);
                sK[(d+3)*SKST + key] = f2tf(v.w);
            }
            const float* vs = qbase + (size_t)(kt*KT + key) * QKVD + 128 + quarter*16;
            unsigned* vd = sV + key * SVST + quarter*16;
            #pragma unroll
            for (int c = 0; c < 4; c++)
                *(uint4*)(vd + 4*c) = cvt4(*(const float4*)(vs + 4*c));
        }
        __syncthreads();

        // ---- S = Q K^T (16 rows x 64 keys per warp), Q from registers ----
        float S[8][4];
        #pragma unroll
        for (int nt = 0; nt < 8; nt++)
            #pragma unroll
            for (int q = 0; q < 4; q++) S[nt][q] = 0.f;
        #pragma unroll
        for (int kc = 0; kc < 8; kc++) {
            #pragma unroll
            for (int nt = 0; nt < 8; nt++) {
                unsigned bb[2];
                int nb = nt*8 + (lane >> 2);
                bb[0] = sK[(kc*8     + (lane & 3)) * SKST + nb];
                bb[1] = sK[(kc*8 + 4 + (lane & 3)) * SKST + nb];
                mma8(S[nt], qf[kc], bb);
            }
        }

        // ---- mask + scale (2 mask words per row per 64-key tile) ----
        uint2 mw0 = *(const uint2*)(pmr0 + kt*2);
        uint2 mw1 = *(const uint2*)(pmr1 + kt*2);
        unsigned q0[2] = {mw0.x, mw0.y};
        unsigned q1[2] = {mw1.x, mw1.y};
        float rm0 = -INFINITY, rm1 = -INFINITY;
        #pragma unroll
        for (int nt = 0; nt < 8; nt++) {
            int j0 = nt*8 + 2*(lane & 3), j1 = j0 + 1;
            S[nt][0] = ((q0[j0>>5] >> (j0&31)) & 1u) ? S[nt][0]*0.125f : -INFINITY;
            S[nt][1] = ((q0[j1>>5] >> (j1&31)) & 1u) ? S[nt][1]*0.125f : -INFINITY;
            S[nt][2] = ((q1[j0>>5] >> (j0&31)) & 1u) ? S[nt][2]*0.125f : -INFINITY;
            S[nt][3] = ((q1[j1>>5] >> (j1&31)) & 1u) ? S[nt][3]*0.125f : -INFINITY;
            rm0 = fmaxf(rm0, fmaxf(S[nt][0], S[nt][1]));
            rm1 = fmaxf(rm1, fmaxf(S[nt][2], S[nt][3]));
        }
        rm0 = fmaxf(rm0, __shfl_xor_sync(0xffffffffu, rm0, 1));
        rm0 = fmaxf(rm0, __shfl_xor_sync(0xffffffffu, rm0, 2));
        rm1 = fmaxf(rm1, __shfl_xor_sync(0xffffffffu, rm1, 1));
        rm1 = fmaxf(rm1, __shfl_xor_sync(0xffffffffu, rm1, 2));

        float mn0 = fmaxf(m0r, rm0), mn1 = fmaxf(m1r, rm1);
        float a0 = __expf(m0r - mn0), a1 = __expf(m1r - mn1);
        m0r = mn0; m1r = mn1;

        // ---- P = exp(S - m), row sums, stash P into sP (own warp rows) ----
        int prow0 = 16*w + (lane >> 2), prow1 = prow0 + 8;
        float rs0 = 0.f, rs1 = 0.f;
        #pragma unroll
        for (int nt = 0; nt < 8; nt++) {
            int j0 = nt*8 + 2*(lane & 3);
            float p00 = __expf(S[nt][0] - mn0), p01 = __expf(S[nt][1] - mn0);
            float p10 = __expf(S[nt][2] - mn1), p11 = __expf(S[nt][3] - mn1);
            rs0 += p00 + p01; rs1 += p10 + p11;
            sP[prow0*SPST + j0]     = f2tf(p00);
            sP[prow0*SPST + j0 + 1] = f2tf(p01);
            sP[prow1*SPST + j0]     = f2tf(p10);
            sP[prow1*SPST + j0 + 1] = f2tf(p11);
        }
        rs0 += __shfl_xor_sync(0xffffffffu, rs0, 1);
        rs0 += __shfl_xor_sync(0xffffffffu, rs0, 2);
        rs1 += __shfl_xor_sync(0xffffffffu, rs1, 1);
        rs1 += __shfl_xor_sync(0xffffffffu, rs1, 2);
        l0r = l0r * a0 + rs0;
        l1r = l1r * a1 + rs1;

        #pragma unroll
        for (int j = 0; j < 8; j++) {
            accO[j][0] *= a0; accO[j][1] *= a0;
            accO[j][2] *= a1; accO[j][3] *= a1;
        }
        __syncwarp();

        // ---- O += P @ V (P rows owned by this warp only) ----
        #pragma unroll
        for (int kc = 0; kc < 8; kc++) {
            unsigned pf[4];
            ldsm4(pf[0], pf[1], pf[2], pf[3],
                  sPb + 4u * (unsigned)(arow * SPST + kc*8 + (mi >> 1) * 4));
            #pragma unroll
            for (int nt = 0; nt < 8; nt++) {
                unsigned bb[2];
                int nb = nt*8 + (lane >> 2);
                bb[0] = sV[(kc*8     + (lane & 3)) * SVST + nb];
                bb[1] = sV[(kc*8 + 4 + (lane & 3)) * SVST + nb];
                mma8(accO[nt], pf, bb);
            }
        }
    }

    // ---- epilogue: O /= l, write to g_o[b, i, h*64 + d] ----
    float inv0 = 1.f / l0r, inv1 = 1.f / l1r;
    int r0 = m0 + 16*w + (lane >> 2), r1 = r0 + 8;
    float* o0 = g_o + (size_t)(b*LL + r0) * NHID + h*64;
    float* o1 = g_o + (size_t)(b*LL + r1) * NHID + h*64;
    #pragma unroll
    for (int nt = 0; nt < 8; nt++) {
        int col = nt*8 + 2*(lane & 3);
        *(float2*)(o0 + col) = make_float2(accO[nt][0]*inv0, accO[nt][1]*inv0);
        *(float2*)(o1 + col) = make_float2(accO[nt][2]*inv1, accO[nt][3]*inv1);
    }
}

// pack mask (int32 bool, layout [b][i][h][j]) -> bits [b][h][i][j/32]
__global__ void k_packmask(const int* __restrict__ mask) {
    int row = blockIdx.x * 8 + (threadIdx.x >> 5);   // (b*512 + i)*8 + h
    int lane = threadIdx.x & 31;
    const int* mr = mask + (size_t)row * LL;
    int b_i = row >> 3, h = row & 7;
    int b = b_i >> 9, i = b_i & 511;
    unsigned* out = g_pm + (((size_t)(b*HEADS + h) * LL + i) << 4);
    #pragma unroll
    for (int wd = 0; wd < 16; wd++) {
        unsigned bits = __ballot_sync(0xffffffffu, mr[wd*32 + lane] != 0);
        if (lane == 0) out[wd] = bits;
    }
}

// ----------------------------- small FFMA GEMM (tiny M=1 cases) ------------
__global__ void gemm1_k(GP p) {
    int zo = blockIdx.z;
    const float* A = p.A + zo * p.aO;
    const float* B = p.B + zo * p.bO;
    float* C = p.C + zo * p.cO;
    const float* bias = p.bias ? p.bias + zo * p.biasO : nullptr;
    int n = blockIdx.x * 64 + threadIdx.x;
    if (n >= p.N) return;
    float s = 0.f;
    for (int k = 0; k < p.K; k++) s += A[k] * B[(size_t)k * p.ldb + n];
    if (bias) s += bias[n];
    C[n] = s;
}

// ----------------------------- small kernels -------------------------------
__global__ void k_embed(const float* __restrict__ emb, const float* __restrict__ pos,
                        const int* __restrict__ idxs) {
    int tok = blockIdx.x;
    int b = tok >> 9, s = tok & 511;
    int id = (s == 0) ? 0 : idxs[b*SS + s - 1];
    const float4* e  = (const float4*)(emb + (size_t)id * NHID);
    const float4* pr = (const float4*)(pos + (size_t)s  * NHID);
    float4* hr = (float4*)(g_h + (size_t)tok * NHID);
    int t = threadIdx.x;
    float4 a = e[t], c = pr[t];
    hr[t] = make_float4(a.x+c.x, a.y+c.y, a.z+c.z, a.w+c.w);
}

__global__ void k_ln_add(float* __restrict__ out, const float* __restrict__ inp,
                         const float* __restrict__ base, int hgMap,
                         const float* __restrict__ gw, const float* __restrict__ bw) {
    int n = blockIdx.x;
    const float* xr = inp + (size_t)n * NHID;
    size_t brow;
    if (hgMap) { int b = n / SS, s = n % SS; brow = ((size_t)(b*LL + s + 1)) * NHID; }
    else brow = (size_t)n * NHID;
    int t = threadIdx.x;  // 128
    float x[4];
    #pragma unroll
    for (int i = 0; i < 4; i++) x[i] = xr[t + i*128];
    __shared__ float red[128];
    red[t] = x[0]+x[1]+x[2]+x[3]; __syncthreads();
    for (int s = 64; s > 0; s >>= 1) { if (t < s) red[t] += red[t+s]; __syncthreads(); }
    float mu = red[0] * (1.f/512.f); __syncthreads();
    float d[4], vs = 0.f;
    #pragma unroll
    for (int i = 0; i < 4; i++) { d[i] = x[i] - mu; vs += d[i]*d[i]; }
    red[t] = vs; __syncthreads();
    for (int s = 64; s > 0; s >>= 1) { if (t < s) red[t] += red[t+s]; __syncthreads(); }
    float inv = rsqrtf(red[0] * (1.f/512.f) + 1e-5f);
    #pragma unroll
    for (int i = 0; i < 4; i++) {
        int c = t + i*128;
        out[(size_t)n*NHID + c] = base[brow + c] + d[i]*inv*gw[c] + bw[c];
    }
}

__global__ void k_zg(float* __restrict__ dout) {
    int b = blockIdx.x; int t = threadIdx.x;
    #pragma unroll
    for (int i = 0; i < 4; i++) {
        int c = t + i*128;
        dout[(size_t)NNODE*NHID + b*NHID + c] = g_h[((size_t)b*LL) * NHID + c];
    }
}

__global__ void k_copyxf() {
    int n = blockIdx.x;
    int b = n / SS, s = n % SS;
    const float4* src = (const float4*)(g_h + ((size_t)(b*LL + s + 1)) * NHID);
    float4* dst = (float4*)(g_xf + (size_t)n * NHID);
    dst[threadIdx.x] = src[threadIdx.x];
}

__global__ void k_zero_ints() {
    int i = blockIdx.x*blockDim.x + threadIdx.x;
    if (i < 2*NNODE) { g_ind[i] = 0; g_outd[i] = 0; g_cur[i] = 0; }
}

__global__ void k_count(const int* __restrict__ src, const int* __restrict__ dst, int gi) {
    int e = blockIdx.x*blockDim.x + threadIdx.x;
    if (e < EE) {
        atomicAdd(&g_ind [gi*NNODE + dst[e]], 1);
        atomicAdd(&g_outd[gi*NNODE + src[e]], 1);
    }
}

__global__ void k_scan(int gi) {
    __shared__ int sh[1024];
    int t = threadIdx.x;
    int base = gi * NNODE;
    int loc[8]; int sum = 0;
    #pragma unroll
    for (int i = 0; i < 8; i++) {
        int idx = t*8 + i;
        int v = (idx < NNODE) ? g_ind[base + idx] : 0;
        loc[i] = sum; sum += v;
    }
    sh[t] = sum; __syncthreads();
    for (int d = 1; d < 1024; d <<= 1) {
        int v = (t >= d) ? sh[t-d] : 0; __syncthreads();
        sh[t] += v; __syncthreads();
    }
    int pre = (t > 0) ? sh[t-1] : 0;
    #pragma unroll
    for (int i = 0; i < 8; i++) {
        int idx = t*8 + i;
        if (idx < NNODE) g_off[base + idx] = pre + loc[i];
    }
}

__global__ void k_scatter(const int* __restrict__ src, const int* __restrict__ dst, int gi) {
    int e = blockIdx.x*blockDim.x + threadIdx.x;
    if (e < EE) {
        int d = dst[e];
        int p = g_off[gi*NNODE + d] + atomicAdd(&g_cur[gi*NNODE + d], 1);
        g_csr[gi*EE + p] = src[e];
    }
}

__global__ void k_scales() {
    int i = blockIdx.x*blockDim.x + threadIdx.x;
    if (i < 2*NNODE) {
        float in = (float)g_ind[i], od = (float)g_outd[i];
        g_sin [i] = rsqrtf(fmaxf(in, 1.f));
        g_sout[i] = rsqrtf(fmaxf(od, 1.f));
        g_inv1[i] = 1.f / (in + 1.f);
    }
}

__global__ void k_prop_sage(const float* __restrict__ x, float* __restrict__ out, int gi) {
    int wid = blockIdx.x * (blockDim.x >> 5) + (threadIdx.x >> 5);
    if (wid >= NNODE) return;
    int lane = threadIdx.x & 31;
    const float4* xr = (const float4*)(x + (size_t)wid * NHID);
    float4 a0 = xr[lane], a1 = xr[lane+32], a2 = xr[lane+64], a3 = xr[lane+96];
    int s = g_off[gi*NNODE + wid], e = s + g_ind[gi*NNODE + wid];
    const int* csr = g_csr + gi*EE;
    for (int j = s; j < e; j++) {
        int sn = csr[j];
        const float4* sr = (const float4*)(x + (size_t)sn * NHID);
        float4 v;
        v = sr[lane];    a0.x+=v.x; a0.y+=v.y; a0.z+=v.z; a0.w+=v.w;
        v = sr[lane+32]; a1.x+=v.x; a1.y+=v.y; a1.z+=v.z; a1.w+=v.w;
        v = sr[lane+64]; a2.x+=v.x; a2.y+=v.y; a2.z+=v.z; a2.w+=v.w;
        v = sr[lane+96]; a3.x+=v.x; a3.y+=v.y; a3.z+=v.z; a3.w+=v.w;
    }
    float sc = g_inv1[gi*NNODE + wid];
    float4* o = (float4*)(out + (size_t)wid * NHID);
    a0.x*=sc; a0.y*=sc; a0.z*=sc; a0.w*=sc; o[lane]    = a0;
    a1.x*=sc; a1.y*=sc; a1.z*=sc; a1.w*=sc; o[lane+32] = a1;
    a2.x*=sc; a2.y*=sc; a2.z*=sc; a2.w*=sc; o[lane+64] = a2;
    a3.x*=sc; a3.y*=sc; a3.z*=sc; a3.w*=sc; o[lane+96] = a3;
}

__global__ void k_prop_gc(const float* __restrict__ q, float* __restrict__ outT, int gi) {
    int wid = blockIdx.x * (blockDim.x >> 5) + (threadIdx.x >> 5);
    if (wid >= NNODE) return;
    int lane = threadIdx.x & 31;
    float4 a0 = make_float4(0,0,0,0), a1 = a0, a2 = a0, a3 = a0;
    float ts = 0.f;
    int s = g_off[gi*NNODE + wid], e = s + g_ind[gi*NNODE + wid];
    const int* csr = g_csr + gi*EE;
    for (int j = s; j < e; j++) {
        int sn = csr[j];
        float so = g_sout[gi*NNODE + sn];
        ts += so;
        const float4* sr = (const float4*)(q + (size_t)sn * NHID);
        float4 v;
        v = sr[lane];    a0.x+=v.x*so; a0.y+=v.y*so; a0.z+=v.z*so; a0.w+=v.w*so;
        v = sr[lane+32]; a1.x+=v.x*so; a1.y+=v.y*so; a1.z+=v.z*so; a1.w+=v.w*so;
        v = sr[lane+64]; a2.x+=v.x*so; a2.y+=v.y*so; a2.z+=v.z*so; a2.w+=v.w*so;
        v = sr[lane+96]; a3.x+=v.x*so; a3.y+=v.y*so; a3.z+=v.z*so; a3.w+=v.w*so;
    }
    float4* o = (float4*)(outT + (size_t)wid * NHID);
    o[lane] = a0; o[lane+32] = a1; o[lane+64] = a2; o[lane+96] = a3;
    if (lane == 0) g_tvec[gi*NNODE + wid] = ts;
}

__global__ void k_xcepi(const float* __restrict__ gc3b) {
    int n = blockIdx.x; int c = threadIdx.x;
    int g = c_pat[c >> 6];
    float si = g_sin[g*NNODE + n], tv = g_tvec[g*NNODE + n];
    size_t idx = (size_t)n*NHID + c;
    g_xc[idx] = si * g_xc[idx] + si * tv * g_dcat[c] + gc3b[c];
}

// ----------------------------- host orchestration --------------------------
#define SYM(name, var) { void* _p; cudaGetSymbolAddress(&_p, name); var = (float*)_p; }

extern "C" void kernel_launch(void* const* d_in, const int* in_sizes, int n_in,
                              void* d_out, int out_size) {
    const float* in_embed  = (const float*)d_in[0];
    const float* pos_embed = (const float*)d_in[1];
    const float* qkv_w     = (const float*)d_in[2];
    const float* qkv_b     = (const float*)d_in[3];
    const float* attn_w    = (const float*)d_in[4];
    const float* attn_b    = (const float*)d_in[5];
    const float* ff1_w     = (const float*)d_in[6];
    const float* ff1_b     = (const float*)d_in[7];
    const float* ff2_w     = (const float*)d_in[8];
    const float* ff2_b     = (const float*)d_in[9];
    const float* sage1_w   = (const float*)d_in[10];
    const float* sage1_b   = (const float*)d_in[11];
    const float* sage2_w   = (const float*)d_in[12];
    const float* sage2_b   = (const float*)d_in[13];
    const float* gc3_w     = (const float*)d_in[14];
    const float* gc3_b     = (const float*)d_in[15];
    const float* gff1_w    = (const float*)d_in[16];
    const float* gff1_b    = (const float*)d_in[17];
    const float* gff2_w    = (const float*)d_in[18];
    const float* gff2_b    = (const float*)d_in[19];
    const float* ln_g      = (const float*)d_in[20];
    const float* ln_b      = (const float*)d_in[21];
    const int*   in_idxs   = (const int*)d_in[22];
    const int*   mask      = (const int*)d_in[23];   // bool marshalled as int32
    const int*   gt_src    = (const int*)d_in[24];
    const int*   gt_dst    = (const int*)d_in[25];
    const int*   at_src    = (const int*)d_in[26];
    const int*   at_dst    = (const int*)d_in[27];

    float *h, *qkv, *o, *x, *ff, *xf, *P, *Q, *T, *xc, *xg, *fg, *Mb, *Nc, *cc, *dc;
    SYM(g_h, h); SYM(g_qkv, qkv); SYM(g_o, o); SYM(g_x, x); SYM(g_ff, ff);
    SYM(g_xf, xf); SYM(g_P, P); SYM(g_Q, Q); SYM(g_T, T); SYM(g_xc, xc); SYM(g_xg, xg);
    SYM(g_fg, fg); SYM(g_M, Mb); SYM(g_Ncat, Nc); SYM(g_ccat, cc); SYM(g_dcat, dc);

    static int smemSet = 0;
    if (!smemSet) {
        cudaFuncSetAttribute(k_flash, cudaFuncAttributeMaxDynamicSharedMemorySize, FLASH_SMEM);
        smemSet = 1;
    }

    // ---- embedding + mask packing ----
    k_embed<<<NTOK, 128>>>(in_embed, pos_embed, in_idxs);
    k_packmask<<<BB*LL*HEADS/8, 256>>>(mask);

    // ---- transformer layers ----
    for (int l = 0; l < 4; l++) {
        // qkv = h @ W + b
        mgemm(h, NHID, qkv_w + (size_t)l*NHID*QKVD, QKVD, qkv, QKVD,
              NTOK, QKVD, NHID, qkv_b + l*QKVD);
        // fused attention: o = softmax(mask, QK^T/8) @ V
        k_flash<<<dim3(LL/128, BB*HEADS), 256, FLASH_SMEM>>>();
        // x = 2h + (o @ Wout + b)
        mgemm(o, NHID, attn_w + (size_t)l*NHID*NHID, NHID, x, NHID,
              NTOK, NHID, NHID, attn_b + l*NHID, h, NHID, 2.0f);
        // ff = relu(x @ W1 + b1)
        mgemm(x, NHID, ff1_w + (size_t)l*NHID*FFD, FFD, ff, FFD,
              NTOK, FFD, NHID, ff1_b + l*FFD, nullptr, 0, 0.f, /*relu=*/1);
        // h = x + (ff @ W2 + b2)
        mgemm(ff, FFD, ff2_w + (size_t)l*FFD*NHID, NHID, h, NHID,
              NTOK, NHID, FFD, ff2_b + l*NHID, x, NHID, 1.0f);
    }

    // ---- graph preprocessing ----
    k_zero_ints<<<(2*NNODE + 255)/256, 256>>>();
    k_count<<<EE/256, 256>>>(gt_src, gt_dst, 0);
    k_count<<<EE/256, 256>>>(at_src, at_dst, 1);
    k_scan<<<1, 1024>>>(0);
    k_scan<<<1, 1024>>>(1);
    k_scatter<<<EE/256, 256>>>(gt_src, gt_dst, 0);
    k_scatter<<<EE/256, 256>>>(at_src, at_dst, 1);
    k_scales<<<(2*NNODE + 255)/256, 256>>>();
    k_copyxf<<<NNODE, 128>>>();

    // ---- propagations (3 per graph) ----
    int propBlocks = (NNODE + 7) / 8;
    for (int g = 0; g < 2; g++) {
        k_prop_sage<<<propBlocks, 256>>>(xf, P, g);
        k_prop_sage<<<propBlocks, 256>>>(P,  Q, g);
        k_prop_gc  <<<propBlocks, 256>>>(Q,  T + (size_t)g*NNODE*NHID, g);
    }

    // ---- collapse per-head weights: M_i = W1 W2, N_i = M_i W3, c_i, d_i ----
    mgemm(sage1_w, NHID, sage2_w, NHID, Mb, NHID, NHID, NHID, NHID,
          nullptr, nullptr, 0, 0.f, 0, 0, HEADS, 1,
          (long long)NHID*NHID, 0, (long long)NHID*NHID, 0, (long long)NHID*NHID, 0);
    mgemm(Mb, NHID, gc3_w, 64, Nc, 64, NHID, 64, NHID,
          nullptr, nullptr, 0, 0.f, 0, 0, HEADS, 1,
          (long long)NHID*NHID, 0, (long long)NHID*64, 0, (long long)NHID*64, 0);
    {
        GP p; p.A=sage1_b; p.B=sage2_w; p.bias=sage2_b; p.res=nullptr; p.C=cc;
        p.lda=NHID; p.ldb=NHID; p.ldc=NHID; p.ldres=0;
        p.M=1; p.N=NHID; p.K=NHID; p.resScale=0; p.relu=0; p.zDiv=1; p.hmode=0;
        p.aO=NHID; p.bO=(long long)NHID*NHID; p.cO=NHID; p.biasO=NHID;
        p.aI=p.bI=p.cI=p.rO=p.rI=0;
        gemm1_k<<<dim3((NHID+63)/64,1,HEADS), 64>>>(p);
    }
    {
        GP p; p.A=cc; p.B=gc3_w; p.bias=nullptr; p.res=nullptr; p.C=dc;
        p.lda=NHID; p.ldb=64; p.ldc=64; p.ldres=0;
        p.M=1; p.N=64; p.K=NHID; p.resScale=0; p.relu=0; p.zDiv=1; p.hmode=0;
        p.aO=NHID; p.bO=(long long)NHID*64; p.cO=64; p.biasO=0;
        p.aI=p.bI=p.cI=p.rO=p.rI=0;
        gemm1_k<<<dim3(1,1,HEADS), 64>>>(p);
    }

    // ---- xc per head: one launch, A = T[(z>>1)&1], via hmode ----
    mgemm(T, NHID, Nc, 64, xc, NHID,
          NNODE, 64, NHID, nullptr, nullptr, 0, 0.f, 0, 0,
          HEADS, 1,
          0, (long long)NNODE*NHID,
          (long long)NHID*64, 0,
          64, 0, 0, 0, 0, /*hmode=*/1);
    k_xcepi<<<NNODE, 512>>>(gc3_b);

    // ---- final: x = hg + LN(xc); ff = relu(x W1+b) W2 + b; zbar = x + LN(ff) ----
    k_ln_add<<<NNODE, 128>>>(xg, xc, h, /*hgMap=*/1, ln_g, ln_b);
    mgemm(xg, NHID, gff1_w, NHID, fg, NHID, NNODE, NHID, NHID, gff1_b,
          nullptr, 0, 0.f, /*relu=*/1);
    mgemm(fg, NHID, gff2_w, NHID, xc, NHID, NNODE, NHID, NHID, gff2_b);
    k_ln_add<<<NNODE, 128>>>((float*)d_out, xc, xg, /*hgMap=*/0, ln_g, ln_b);

    // ---- zg ----
    if (out_size >= NNODE*NHID + BB*NHID)
        k_zg<<<BB, 128>>>((float*)d_out);
}

// round 6
// speedup vs baseline: 3.0158x; 1.0173x over previous
#include <cuda_runtime.h>
#include <math.h>
#include <stdint.h>

#define NHID   512
#define HEADS  8
#define NKD    64
#define BB     16
#define SS     511
#define LL     512
#define NNODE  8176      // BB*SS
#define NTOK   8192      // BB*LL
#define EE     131072
#define QKVD   1536
#define FFD    2048

// ----------------------------- scratch (device globals; no allocation) -----
__device__ float g_h   [NTOK*NHID];
__device__ float g_qkv [NTOK*QKVD];
__device__ float g_o   [NTOK*NHID];
__device__ float g_x   [NTOK*NHID];
__device__ float g_ff  [NTOK*FFD];
__device__ float g_xf  [NNODE*NHID];
__device__ float g_P   [NNODE*NHID];
__device__ float g_Q   [NNODE*NHID];
__device__ float g_T   [2*NNODE*NHID];
__device__ float g_xc  [NNODE*NHID];
__device__ float g_xg  [NNODE*NHID];
__device__ float g_fg  [NNODE*NHID];
__device__ float g_M   [HEADS*NHID*NHID];
__device__ float g_Ncat[HEADS*NHID*64];
__device__ float g_ccat[HEADS*NHID];
__device__ float g_dcat[HEADS*64];
__device__ float g_tvec[2*NNODE];
__device__ float g_sin [2*NNODE];
__device__ float g_sout[2*NNODE];
__device__ float g_inv1[2*NNODE];
__device__ int   g_ind [2*NNODE];
__device__ int   g_outd[2*NNODE];
__device__ int   g_off [2*NNODE];
__device__ int   g_cur [2*NNODE];
__device__ int   g_csr [2*EE];
__device__ unsigned g_pm[(size_t)BB*HEADS*LL*(LL/32)];   // packed mask bits (4 MB)

__constant__ int c_pat[8] = {0,0,1,1,0,0,1,1};

// ----------------------------- common GEMM param block ---------------------
struct GP {
    const float *A, *B, *bias, *res;
    float *C;
    int lda, ldb, ldc, ldres;
    int M, N, K;
    float resScale;
    int relu;
    int zDiv;
    int hmode;     // per-head graph GEMM mode: A selected by (z>>1)&1
    long long aO, aI, bO, bI, cO, cI, rO, rI, biasO;
};

// ----------------------------- tf32 helpers --------------------------------
__device__ __forceinline__ unsigned f2tf(float f) {
    unsigned u; asm("cvt.rna.tf32.f32 %0, %1;" : "=r"(u) : "f"(f)); return u;
}
__device__ __forceinline__ uint4 cvt4(float4 v) {
    uint4 r; r.x=f2tf(v.x); r.y=f2tf(v.y); r.z=f2tf(v.z); r.w=f2tf(v.w); return r;
}
__device__ __forceinline__ void ldsm4(unsigned &d0, unsigned &d1, unsigned &d2, unsigned &d3,
                                      unsigned addr) {
    asm volatile("ldmatrix.sync.aligned.m8n8.x4.shared.b16 {%0,%1,%2,%3}, [%4];"
                 : "=r"(d0), "=r"(d1), "=r"(d2), "=r"(d3) : "r"(addr));
}
__device__ __forceinline__ void mma8(float* c, const unsigned* a, const unsigned* b) {
    asm volatile(
        "mma.sync.aligned.m16n8k8.row.col.f32.tf32.tf32.f32 "
        "{%0,%1,%2,%3}, {%4,%5,%6,%7}, {%8,%9}, {%0,%1,%2,%3};"
        : "+f"(c[0]), "+f"(c[1]), "+f"(c[2]), "+f"(c[3])
        : "r"(a[0]), "r"(a[1]), "r"(a[2]), "r"(a[3]), "r"(b[0]), "r"(b[1]));
}

// ----------------------------- tf32 tensor-core GEMM (2-stage) -------------
// CTA tile 128 x BN, 8 warps, K-slice 16, double-buffered smem:
// one barrier per K-iter; next-stage store + next-next prefetch issue
// ahead of current-stage MMAs.
template<int BN, int WGN, bool TB>
__global__ __launch_bounds__(256) void mma_k(GP p) {
    constexpr int WGM = 8 / WGN;
    constexpr int WM  = 128 / WGM;
    constexpr int WN  = BN / WGN;
    constexpr int MF  = WM / 16;
    constexpr int NF  = WN / 8;
    constexpr int AST = 20;        // A smem row stride (words), conflict-free ldmatrix
    constexpr int BST = BN + 8;    // B smem row stride: =8 mod 32 -> conflict-free LDS

    __shared__ unsigned sA[2][128 * AST];
    __shared__ unsigned sB[2][16 * BST];

    const float *A, *B; float *C;
    const float *bias = nullptr, *res = nullptr;
    if (p.hmode) {
        int hd = blockIdx.z;
        A = p.A + (((hd >> 1) & 1) ? p.aI : 0);
        B = p.B + (size_t)hd * p.bO;
        C = p.C + (size_t)hd * p.cO;
    } else {
        int zo = blockIdx.z / p.zDiv, zi = blockIdx.z % p.zDiv;
        A = p.A + zo * p.aO + zi * p.aI;
        B = p.B + zo * p.bO + zi * p.bI;
        C = p.C + zo * p.cO + zi * p.cI;
        if (p.bias) bias = p.bias + zo * p.biasO;
        if (p.res)  res  = p.res + zo * p.rO + zi * p.rI;
    }

    int tid = threadIdx.x, lane = tid & 31, warp = tid >> 5;
    int wm = warp / WGN, wn = warp % WGN;
    int m0 = blockIdx.x * 128, n0 = blockIdx.y * BN;

    int ar = tid >> 1, ak = (tid & 1) * 8;
    bool aval = (m0 + ar) < p.M;
    const float* aptr = A + (size_t)(m0 + ar) * p.lda + ak;

    const float* bptr;
    int bn_t = 0, bk_t = 0, bn4_t = 0;
    if (TB) {
        bn_t = tid >> 1; bk_t = (tid & 1) * 8;
        bptr = B + (size_t)(n0 + bn_t) * p.ldb + bk_t;
    } else if (BN == 128) {
        bk_t = tid >> 5; bn4_t = (tid & 31) * 4;
        bptr = B + (size_t)bk_t * p.ldb + n0 + bn4_t;
    } else {
        bk_t = tid >> 4; bn4_t = (tid & 15) * 4;
        bptr = B + (size_t)bk_t * p.ldb + n0 + bn4_t;
    }

    float acc[MF][NF][4];
    #pragma unroll
    for (int f = 0; f < MF; f++)
        #pragma unroll
        for (int j = 0; j < NF; j++)
            #pragma unroll
            for (int q = 0; q < 4; q++) acc[f][j][q] = 0.f;

    float4 pa0, pa1, pb0, pb1;
    pa0 = pa1 = pb0 = pb1 = make_float4(0.f,0.f,0.f,0.f);

    auto loadRegs = [&](int k0) {
        if (aval) { pa0 = *(const float4*)(aptr + k0); pa1 = *(const float4*)(aptr + k0 + 4); }
        if (TB)             { pb0 = *(const float4*)(bptr + k0); pb1 = *(const float4*)(bptr + k0 + 4); }
        else if (BN == 128) { pb0 = *(const float4*)(bptr + (size_t)k0 * p.ldb);
                              pb1 = *(const float4*)(bptr + (size_t)(k0 + 8) * p.ldb); }
        else                { pb0 = *(const float4*)(bptr + (size_t)k0 * p.ldb); }
    };
    auto storeStage = [&](int s) {
        unsigned* A_ = sA[s];
        unsigned* B_ = sB[s];
        *(uint4*)&A_[ar * AST + ak]     = cvt4(pa0);
        *(uint4*)&A_[ar * AST + ak + 4] = cvt4(pa1);
        if (TB) {
            B_[(bk_t + 0) * BST + bn_t] = f2tf(pb0.x);
            B_[(bk_t + 1) * BST + bn_t] = f2tf(pb0.y);
            B_[(bk_t + 2) * BST + bn_t] = f2tf(pb0.z);
            B_[(bk_t + 3) * BST + bn_t] = f2tf(pb0.w);
            B_[(bk_t + 4) * BST + bn_t] = f2tf(pb1.x);
            B_[(bk_t + 5) * BST + bn_t] = f2tf(pb1.y);
            B_[(bk_t + 6) * BST + bn_t] = f2tf(pb1.z);
            B_[(bk_t + 7) * BST + bn_t] = f2tf(pb1.w);
        } else if (BN == 128) {
            *(uint4*)&B_[bk_t * BST + bn4_t]       = cvt4(pb0);
            *(uint4*)&B_[(bk_t + 8) * BST + bn4_t] = cvt4(pb1);
        } else {
            *(uint4*)&B_[bk_t * BST + bn4_t] = cvt4(pb0);
        }
    };

    // prologue: fill stage 0, prefetch iter 1 into regs
    loadRegs(0);
    storeStage(0);
    if (16 < p.K) loadRegs(16);
    __syncthreads();

    int cur = 0;
    for (int k0 = 0; k0 < p.K; k0 += 16) {
        int nxt = cur ^ 1;
        // store next stage (regs hold k0+16 data) before MMAs; overlaps with tensor work
        if (k0 + 16 < p.K) storeStage(nxt);
        // prefetch k0+32 into regs; hides global latency behind MMAs
        if (k0 + 32 < p.K) loadRegs(k0 + 32);

        unsigned sAb = (unsigned)__cvta_generic_to_shared(sA[cur]);
        const unsigned* Bc = sB[cur];
        #pragma unroll
        for (int kk = 0; kk < 16; kk += 8) {
            unsigned bfr[NF][2];
            #pragma unroll
            for (int j = 0; j < NF; j++) {
                int nb = wn * WN + j * 8 + (lane >> 2);
                bfr[j][0] = Bc[(kk + (lane & 3)) * BST + nb];
                bfr[j][1] = Bc[(kk + 4 + (lane & 3)) * BST + nb];
            }
            #pragma unroll
            for (int f = 0; f < MF; f++) {
                int mi = lane >> 3, r = lane & 7;
                int row = wm * WM + f * 16 + r + (mi & 1) * 8;
                unsigned addr = sAb + 4u * (unsigned)(row * AST + kk + (mi >> 1) * 4);
                unsigned afr[4];
                ldsm4(afr[0], afr[1], afr[2], afr[3], addr);
                #pragma unroll
                for (int j = 0; j < NF; j++) mma8(acc[f][j], afr, bfr[j]);
            }
        }
        __syncthreads();
        cur = nxt;
    }

    #pragma unroll
    for (int f = 0; f < MF; f++) {
        int r0 = m0 + wm * WM + f * 16 + (lane >> 2);
        int r1 = r0 + 8;
        #pragma unroll
        for (int j = 0; j < NF; j++) {
            int col = n0 + wn * WN + j * 8 + 2 * (lane & 3);
            float b0 = 0.f, b1 = 0.f;
            if (bias) { b0 = bias[col]; b1 = bias[col + 1]; }
            float v0 = acc[f][j][0] + b0, v1 = acc[f][j][1] + b1;
            float v2 = acc[f][j][2] + b0, v3 = acc[f][j][3] + b1;
            if (p.relu) {
                v0 = fmaxf(v0, 0.f); v1 = fmaxf(v1, 0.f);
                v2 = fmaxf(v2, 0.f); v3 = fmaxf(v3, 0.f);
            }
            if (r0 < p.M) {
                if (res) {
                    v0 += p.resScale * res[(size_t)r0 * p.ldres + col];
                    v1 += p.resScale * res[(size_t)r0 * p.ldres + col + 1];
                }
                *(float2*)&C[(size_t)r0 * p.ldc + col] = make_float2(v0, v1);
            }
            if (r1 < p.M) {
                if (res) {
                    v2 += p.resScale * res[(size_t)r1 * p.ldres + col];
                    v3 += p.resScale * res[(size_t)r1 * p.ldres + col + 1];
                }
                *(float2*)&C[(size_t)r1 * p.ldc + col] = make_float2(v2, v3);
            }
        }
    }
}

static void mgemm(const float* A, int lda, const float* B, int ldb, float* C, int ldc,
                  int M, int N, int K,
                  const float* bias = nullptr, const float* res = nullptr, int ldres = 0,
                  float resScale = 0.f, int relu = 0, int transB = 0,
                  int z = 1, int zDiv = 1,
                  long long aO=0, long long aI=0, long long bO=0, long long bI=0,
                  long long cO=0, long long cI=0, long long rO=0, long long rI=0,
                  long long biasO=0, int hmode = 0) {
    GP p;
    p.A=A; p.B=B; p.bias=bias; p.res=res; p.C=C;
    p.lda=lda; p.ldb=ldb; p.ldc=ldc; p.ldres=ldres;
    p.M=M; p.N=N; p.K=K; p.resScale=resScale; p.relu=relu; p.zDiv=zDiv; p.hmode=hmode;
    p.aO=aO; p.aI=aI; p.bO=bO; p.bI=bI; p.cO=cO; p.cI=cI; p.rO=rO; p.rI=rI; p.biasO=biasO;
    if (transB) {
        dim3 grid((M + 127) / 128, N / 128, z);
        mma_k<128, 4, true><<<grid, 256>>>(p);
    } else if (N % 128 == 0) {
        dim3 grid((M + 127) / 128, N / 128, z);
        mma_k<128, 4, false><<<grid, 256>>>(p);
    } else {
        dim3 grid((M + 127) / 128, N / 64, z);
        mma_k<64, 2, false><<<grid, 256>>>(p);
    }
}

// ----------------------------- fused flash attention v2 --------------------
// grid (L/128, B*H), 256 threads (8 warps), warp owns 16 Q rows.
// Q register-resident; K-tiles of 64 keys. smem 70 KB, 2 CTAs/SM.
#define KT     64
#define SKST   72
#define SVST   72
#define SPST   68
#define FLASH_SMEM ((64*SKST + 64*SVST + 128*SPST) * 4)

__global__ __launch_bounds__(256, 2) void k_flash() {
    extern __shared__ unsigned sm[];
    unsigned* sK = sm;
    unsigned* sV = sK + 64*SKST;
    unsigned* sP = sV + 64*SVST;

    int tid = threadIdx.x, lane = tid & 31, w = tid >> 5;
    int m0 = blockIdx.x * 128;
    int bh = blockIdx.y; int h = bh & 7, b = bh >> 3;
    const float* qbase = g_qkv + (size_t)(b * LL) * QKVD + h * 192;

    unsigned sPb = (unsigned)__cvta_generic_to_shared(sP);
    int mi = lane >> 3, rr = lane & 7;
    int arow = 16*w + rr + (mi & 1) * 8;

    // ---- stage Q tile through sP, then pull fragments into registers ----
    {
        int row = tid >> 1, half = tid & 1;
        const float* src = qbase + (size_t)(m0 + row) * QKVD + half * 32;
        unsigned* dst = sP + row * SPST + half * 32;
        #pragma unroll
        for (int c = 0; c < 8; c++)
            *(uint4*)(dst + 4*c) = cvt4(*(const float4*)(src + 4*c));
    }
    __syncthreads();
    unsigned qf[8][4];
    #pragma unroll
    for (int kc = 0; kc < 8; kc++)
        ldsm4(qf[kc][0], qf[kc][1], qf[kc][2], qf[kc][3],
              sPb + 4u * (unsigned)(arow * SPST + kc*8 + (mi >> 1) * 4));
    __syncthreads();   // all warps done reading Q before sP is reused for P

    float accO[8][4];
    #pragma unroll
    for (int j = 0; j < 8; j++)
        #pragma unroll
        for (int q = 0; q < 4; q++) accO[j][q] = 0.f;
    float m0r = -INFINITY, m1r = -INFINITY, l0r = 0.f, l1r = 0.f;

    const unsigned* pmr0 = g_pm + ((size_t)bh * LL + m0 + 16*w + (lane >> 2)) * 16;
    const unsigned* pmr1 = pmr0 + 8 * 16;

    for (int kt = 0; kt < 8; kt++) {
        __syncthreads();
        {
            int key = tid >> 2, quarter = tid & 3;
            const float* ks = qbase + (size_t)(kt*KT + key) * QKVD + 64 + quarter*16;
            #pragma unroll
            for (int c = 0; c < 4; c++) {
                float4 v = *(const float4*)(ks + 4*c);
                int d = quarter*16 + 4*c;
                sK[(d+0)*SKST + key] = f2tf(v.x);
                sK[(d+1)*SKST + key] = f2tf(v.y);
                sK[(d+2)*SKST + key] = f2tf(v.z);
                sK[(d+3)*SKST + key] = f2tf(v.w);
            }
            const float* vs = qbase + (size_t)(kt*KT + key) * QKVD + 128 + quarter*16;
            unsigned* vd = sV + key * SVST + quarter*16;
            #pragma unroll
            for (int c = 0; c < 4; c++)
                *(uint4*)(vd + 4*c) = cvt4(*(const float4*)(vs + 4*c));
        }
        __syncthreads();

        float S[8][4];
        #pragma unroll
        for (int nt = 0; nt < 8; nt++)
            #pragma unroll
            for (int q = 0; q < 4; q++) S[nt][q] = 0.f;
        #pragma unroll
        for (int kc = 0; kc < 8; kc++) {
            #pragma unroll
            for (int nt = 0; nt < 8; nt++) {
                unsigned bb[2];
                int nb = nt*8 + (lane >> 2);
                bb[0] = sK[(kc*8     + (lane & 3)) * SKST + nb];
                bb[1] = sK[(kc*8 + 4 + (lane & 3)) * SKST + nb];
                mma8(S[nt], qf[kc], bb);
            }
        }

        uint2 mw0 = *(const uint2*)(pmr0 + kt*2);
        uint2 mw1 = *(const uint2*)(pmr1 + kt*2);
        unsigned q0[2] = {mw0.x, mw0.y};
        unsigned q1[2] = {mw1.x, mw1.y};
        float rm0 = -INFINITY, rm1 = -INFINITY;
        #pragma unroll
        for (int nt = 0; nt < 8; nt++) {
            int j0 = nt*8 + 2*(lane & 3), j1 = j0 + 1;
            S[nt][0] = ((q0[j0>>5] >> (j0&31)) & 1u) ? S[nt][0]*0.125f : -INFINITY;
            S[nt][1] = ((q0[j1>>5] >> (j1&31)) & 1u) ? S[nt][1]*0.125f : -INFINITY;
            S[nt][2] = ((q1[j0>>5] >> (j0&31)) & 1u) ? S[nt][2]*0.125f : -INFINITY;
            S[nt][3] = ((q1[j1>>5] >> (j1&31)) & 1u) ? S[nt][3]*0.125f : -INFINITY;
            rm0 = fmaxf(rm0, fmaxf(S[nt][0], S[nt][1]));
            rm1 = fmaxf(rm1, fmaxf(S[nt][2], S[nt][3]));
        }
        rm0 = fmaxf(rm0, __shfl_xor_sync(0xffffffffu, rm0, 1));
        rm0 = fmaxf(rm0, __shfl_xor_sync(0xffffffffu, rm0, 2));
        rm1 = fmaxf(rm1, __shfl_xor_sync(0xffffffffu, rm1, 1));
        rm1 = fmaxf(rm1, __shfl_xor_sync(0xffffffffu, rm1, 2));

        float mn0 = fmaxf(m0r, rm0), mn1 = fmaxf(m1r, rm1);
        float a0 = __expf(m0r - mn0), a1 = __expf(m1r - mn1);
        m0r = mn0; m1r = mn1;

        int prow0 = 16*w + (lane >> 2), prow1 = prow0 + 8;
        float rs0 = 0.f, rs1 = 0.f;
        #pragma unroll
        for (int nt = 0; nt < 8; nt++) {
            int j0 = nt*8 + 2*(lane & 3);
            float p00 = __expf(S[nt][0] - mn0), p01 = __expf(S[nt][1] - mn0);
            float p10 = __expf(S[nt][2] - mn1), p11 = __expf(S[nt][3] - mn1);
            rs0 += p00 + p01; rs1 += p10 + p11;
            sP[prow0*SPST + j0]     = f2tf(p00);
            sP[prow0*SPST + j0 + 1] = f2tf(p01);
            sP[prow1*SPST + j0]     = f2tf(p10);
            sP[prow1*SPST + j0 + 1] = f2tf(p11);
        }
        rs0 += __shfl_xor_sync(0xffffffffu, rs0, 1);
        rs0 += __shfl_xor_sync(0xffffffffu, rs0, 2);
        rs1 += __shfl_xor_sync(0xffffffffu, rs1, 1);
        rs1 += __shfl_xor_sync(0xffffffffu, rs1, 2);
        l0r = l0r * a0 + rs0;
        l1r = l1r * a1 + rs1;

        #pragma unroll
        for (int j = 0; j < 8; j++) {
            accO[j][0] *= a0; accO[j][1] *= a0;
            accO[j][2] *= a1; accO[j][3] *= a1;
        }
        __syncwarp();

        #pragma unroll
        for (int kc = 0; kc < 8; kc++) {
            unsigned pf[4];
            ldsm4(pf[0], pf[1], pf[2], pf[3],
                  sPb + 4u * (unsigned)(arow * SPST + kc*8 + (mi >> 1) * 4));
            #pragma unroll
            for (int nt = 0; nt < 8; nt++) {
                unsigned bb[2];
                int nb = nt*8 + (lane >> 2);
                bb[0] = sV[(kc*8     + (lane & 3)) * SVST + nb];
                bb[1] = sV[(kc*8 + 4 + (lane & 3)) * SVST + nb];
                mma8(accO[nt], pf, bb);
            }
        }
    }

    float inv0 = 1.f / l0r, inv1 = 1.f / l1r;
    int r0 = m0 + 16*w + (lane >> 2), r1 = r0 + 8;
    float* o0 = g_o + (size_t)(b*LL + r0) * NHID + h*64;
    float* o1 = g_o + (size_t)(b*LL + r1) * NHID + h*64;
    #pragma unroll
    for (int nt = 0; nt < 8; nt++) {
        int col = nt*8 + 2*(lane & 3);
        *(float2*)(o0 + col) = make_float2(accO[nt][0]*inv0, accO[nt][1]*inv0);
        *(float2*)(o1 + col) = make_float2(accO[nt][2]*inv1, accO[nt][3]*inv1);
    }
}

// pack mask (int32 bool, layout [b][i][h][j]) -> bits [b][h][i][j/32]
__global__ void k_packmask(const int* __restrict__ mask) {
    int row = blockIdx.x * 8 + (threadIdx.x >> 5);   // (b*512 + i)*8 + h
    int lane = threadIdx.x & 31;
    const int* mr = mask + (size_t)row * LL;
    int b_i = row >> 3, h = row & 7;
    int b = b_i >> 9, i = b_i & 511;
    unsigned* out = g_pm + (((size_t)(b*HEADS + h) * LL + i) << 4);
    #pragma unroll
    for (int wd = 0; wd < 16; wd++) {
        unsigned bits = __ballot_sync(0xffffffffu, mr[wd*32 + lane] != 0);
        if (lane == 0) out[wd] = bits;
    }
}

// ----------------------------- small FFMA GEMM (tiny M=1 cases) ------------
__global__ void gemm1_k(GP p) {
    int zo = blockIdx.z;
    const float* A = p.A + zo * p.aO;
    const float* B = p.B + zo * p.bO;
    float* C = p.C + zo * p.cO;
    const float* bias = p.bias ? p.bias + zo * p.biasO : nullptr;
    int n = blockIdx.x * 64 + threadIdx.x;
    if (n >= p.N) return;
    float s = 0.f;
    for (int k = 0; k < p.K; k++) s += A[k] * B[(size_t)k * p.ldb + n];
    if (bias) s += bias[n];
    C[n] = s;
}

// ----------------------------- small kernels -------------------------------
__global__ void k_embed(const float* __restrict__ emb, const float* __restrict__ pos,
                        const int* __restrict__ idxs) {
    int tok = blockIdx.x;
    int b = tok >> 9, s = tok & 511;
    int id = (s == 0) ? 0 : idxs[b*SS + s - 1];
    const float4* e  = (const float4*)(emb + (size_t)id * NHID);
    const float4* pr = (const float4*)(pos + (size_t)s  * NHID);
    float4* hr = (float4*)(g_h + (size_t)tok * NHID);
    int t = threadIdx.x;
    float4 a = e[t], c = pr[t];
    hr[t] = make_float4(a.x+c.x, a.y+c.y, a.z+c.z, a.w+c.w);
}

__global__ void k_ln_add(float* __restrict__ out, const float* __restrict__ inp,
                         const float* __restrict__ base, int hgMap,
                         const float* __restrict__ gw, const float* __restrict__ bw) {
    int n = blockIdx.x;
    const float* xr = inp + (size_t)n * NHID;
    size_t brow;
    if (hgMap) { int b = n / SS, s = n % SS; brow = ((size_t)(b*LL + s + 1)) * NHID; }
    else brow = (size_t)n * NHID;
    int t = threadIdx.x;  // 128
    float x[4];
    #pragma unroll
    for (int i = 0; i < 4; i++) x[i] = xr[t + i*128];
    __shared__ float red[128];
    red[t] = x[0]+x[1]+x[2]+x[3]; __syncthreads();
    for (int s = 64; s > 0; s >>= 1) { if (t < s) red[t] += red[t+s]; __syncthreads(); }
    float mu = red[0] * (1.f/512.f); __syncthreads();
    float d[4], vs = 0.f;
    #pragma unroll
    for (int i = 0; i < 4; i++) { d[i] = x[i] - mu; vs += d[i]*d[i]; }
    red[t] = vs; __syncthreads();
    for (int s = 64; s > 0; s >>= 1) { if (t < s) red[t] += red[t+s]; __syncthreads(); }
    float inv = rsqrtf(red[0] * (1.f/512.f) + 1e-5f);
    #pragma unroll
    for (int i = 0; i < 4; i++) {
        int c = t + i*128;
        out[(size_t)n*NHID + c] = base[brow + c] + d[i]*inv*gw[c] + bw[c];
    }
}

__global__ void k_zg(float* __restrict__ dout) {
    int b = blockIdx.x; int t = threadIdx.x;
    #pragma unroll
    for (int i = 0; i < 4; i++) {
        int c = t + i*128;
        dout[(size_t)NNODE*NHID + b*NHID + c] = g_h[((size_t)b*LL) * NHID + c];
    }
}

__global__ void k_copyxf() {
    int n = blockIdx.x;
    int b = n / SS, s = n % SS;
    const float4* src = (const float4*)(g_h + ((size_t)(b*LL + s + 1)) * NHID);
    float4* dst = (float4*)(g_xf + (size_t)n * NHID);
    dst[threadIdx.x] = src[threadIdx.x];
}

__global__ void k_zero_ints() {
    int i = blockIdx.x*blockDim.x + threadIdx.x;
    if (i < 2*NNODE) { g_ind[i] = 0; g_outd[i] = 0; g_cur[i] = 0; }
}

__global__ void k_count(const int* __restrict__ src, const int* __restrict__ dst, int gi) {
    int e = blockIdx.x*blockDim.x + threadIdx.x;
    if (e < EE) {
        atomicAdd(&g_ind [gi*NNODE + dst[e]], 1);
        atomicAdd(&g_outd[gi*NNODE + src[e]], 1);
    }
}

__global__ void k_scan(int gi) {
    __shared__ int sh[1024];
    int t = threadIdx.x;
    int base = gi * NNODE;
    int loc[8]; int sum = 0;
    #pragma unroll
    for (int i = 0; i < 8; i++) {
        int idx = t*8 + i;
        int v = (idx < NNODE) ? g_ind[base + idx] : 0;
        loc[i] = sum; sum += v;
    }
    sh[t] = sum; __syncthreads();
    for (int d = 1; d < 1024; d <<= 1) {
        int v = (t >= d) ? sh[t-d] : 0; __syncthreads();
        sh[t] += v; __syncthreads();
    }
    int pre = (t > 0) ? sh[t-1] : 0;
    #pragma unroll
    for (int i = 0; i < 8; i++) {
        int idx = t*8 + i;
        if (idx < NNODE) g_off[base + idx] = pre + loc[i];
    }
}

__global__ void k_scatter(const int* __restrict__ src, const int* __restrict__ dst, int gi) {
    int e = blockIdx.x*blockDim.x + threadIdx.x;
    if (e < EE) {
        int d = dst[e];
        int p = g_off[gi*NNODE + d] + atomicAdd(&g_cur[gi*NNODE + d], 1);
        g_csr[gi*EE + p] = src[e];
    }
}

__global__ void k_scales() {
    int i = blockIdx.x*blockDim.x + threadIdx.x;
    if (i < 2*NNODE) {
        float in = (float)g_ind[i], od = (float)g_outd[i];
        g_sin [i] = rsqrtf(fmaxf(in, 1.f));
        g_sout[i] = rsqrtf(fmaxf(od, 1.f));
        g_inv1[i] = 1.f / (in + 1.f);
    }
}

__global__ void k_prop_sage(const float* __restrict__ x, float* __restrict__ out, int gi) {
    int wid = blockIdx.x * (blockDim.x >> 5) + (threadIdx.x >> 5);
    if (wid >= NNODE) return;
    int lane = threadIdx.x & 31;
    const float4* xr = (const float4*)(x + (size_t)wid * NHID);
    float4 a0 = xr[lane], a1 = xr[lane+32], a2 = xr[lane+64], a3 = xr[lane+96];
    int s = g_off[gi*NNODE + wid], e = s + g_ind[gi*NNODE + wid];
    const int* csr = g_csr + gi*EE;
    for (int j = s; j < e; j++) {
        int sn = csr[j];
        const float4* sr = (const float4*)(x + (size_t)sn * NHID);
        float4 v;
        v = sr[lane];    a0.x+=v.x; a0.y+=v.y; a0.z+=v.z; a0.w+=v.w;
        v = sr[lane+32]; a1.x+=v.x; a1.y+=v.y; a1.z+=v.z; a1.w+=v.w;
        v = sr[lane+64]; a2.x+=v.x; a2.y+=v.y; a2.z+=v.z; a2.w+=v.w;
        v = sr[lane+96]; a3.x+=v.x; a3.y+=v.y; a3.z+=v.z; a3.w+=v.w;
    }
    float sc = g_inv1[gi*NNODE + wid];
    float4* o = (float4*)(out + (size_t)wid * NHID);
    a0.x*=sc; a0.y*=sc; a0.z*=sc; a0.w*=sc; o[lane]    = a0;
    a1.x*=sc; a1.y*=sc; a1.z*=sc; a1.w*=sc; o[lane+32] = a1;
    a2.x*=sc; a2.y*=sc; a2.z*=sc; a2.w*=sc; o[lane+64] = a2;
    a3.x*=sc; a3.y*=sc; a3.z*=sc; a3.w*=sc; o[lane+96] = a3;
}

__global__ void k_prop_gc(const float* __restrict__ q, float* __restrict__ outT, int gi) {
    int wid = blockIdx.x * (blockDim.x >> 5) + (threadIdx.x >> 5);
    if (wid >= NNODE) return;
    int lane = threadIdx.x & 31;
    float4 a0 = make_float4(0,0,0,0), a1 = a0, a2 = a0, a3 = a0;
    float ts = 0.f;
    int s = g_off[gi*NNODE + wid], e = s + g_ind[gi*NNODE + wid];
    const int* csr = g_csr + gi*EE;
    for (int j = s; j < e; j++) {
        int sn = csr[j];
        float so = g_sout[gi*NNODE + sn];
        ts += so;
        const float4* sr = (const float4*)(q + (size_t)sn * NHID);
        float4 v;
        v = sr[lane];    a0.x+=v.x*so; a0.y+=v.y*so; a0.z+=v.z*so; a0.w+=v.w*so;
        v = sr[lane+32]; a1.x+=v.x*so; a1.y+=v.y*so; a1.z+=v.z*so; a1.w+=v.w*so;
        v = sr[lane+64]; a2.x+=v.x*so; a2.y+=v.y*so; a2.z+=v.z*so; a2.w+=v.w*so;
        v = sr[lane+96]; a3.x+=v.x*so; a3.y+=v.y*so; a3.z+=v.z*so; a3.w+=v.w*so;
    }
    float4* o = (float4*)(outT + (size_t)wid * NHID);
    o[lane] = a0; o[lane+32] = a1; o[lane+64] = a2; o[lane+96] = a3;
    if (lane == 0) g_tvec[gi*NNODE + wid] = ts;
}

__global__ void k_xcepi(const float* __restrict__ gc3b) {
    int n = blockIdx.x; int c = threadIdx.x;
    int g = c_pat[c >> 6];
    float si = g_sin[g*NNODE + n], tv = g_tvec[g*NNODE + n];
    size_t idx = (size_t)n*NHID + c;
    g_xc[idx] = si * g_xc[idx] + si * tv * g_dcat[c] + gc3b[c];
}

// ----------------------------- host orchestration --------------------------
#define SYM(name, var) { void* _p; cudaGetSymbolAddress(&_p, name); var = (float*)_p; }

extern "C" void kernel_launch(void* const* d_in, const int* in_sizes, int n_in,
                              void* d_out, int out_size) {
    const float* in_embed  = (const float*)d_in[0];
    const float* pos_embed = (const float*)d_in[1];
    const float* qkv_w     = (const float*)d_in[2];
    const float* qkv_b     = (const float*)d_in[3];
    const float* attn_w    = (const float*)d_in[4];
    const float* attn_b    = (const float*)d_in[5];
    const float* ff1_w     = (const float*)d_in[6];
    const float* ff1_b     = (const float*)d_in[7];
    const float* ff2_w     = (const float*)d_in[8];
    const float* ff2_b     = (const float*)d_in[9];
    const float* sage1_w   = (const float*)d_in[10];
    const float* sage1_b   = (const float*)d_in[11];
    const float* sage2_w   = (const float*)d_in[12];
    const float* sage2_b   = (const float*)d_in[13];
    const float* gc3_w     = (const float*)d_in[14];
    const float* gc3_b     = (const float*)d_in[15];
    const float* gff1_w    = (const float*)d_in[16];
    const float* gff1_b    = (const float*)d_in[17];
    const float* gff2_w    = (const float*)d_in[18];
    const float* gff2_b    = (const float*)d_in[19];
    const float* ln_g      = (const float*)d_in[20];
    const float* ln_b      = (const float*)d_in[21];
    const int*   in_idxs   = (const int*)d_in[22];
    const int*   mask      = (const int*)d_in[23];   // bool marshalled as int32
    const int*   gt_src    = (const int*)d_in[24];
    const int*   gt_dst    = (const int*)d_in[25];
    const int*   at_src    = (const int*)d_in[26];
    const int*   at_dst    = (const int*)d_in[27];

    float *h, *qkv, *o, *x, *ff, *xf, *P, *Q, *T, *xc, *xg, *fg, *Mb, *Nc, *cc, *dc;
    SYM(g_h, h); SYM(g_qkv, qkv); SYM(g_o, o); SYM(g_x, x); SYM(g_ff, ff);
    SYM(g_xf, xf); SYM(g_P, P); SYM(g_Q, Q); SYM(g_T, T); SYM(g_xc, xc); SYM(g_xg, xg);
    SYM(g_fg, fg); SYM(g_M, Mb); SYM(g_Ncat, Nc); SYM(g_ccat, cc); SYM(g_dcat, dc);

    static int smemSet = 0;
    if (!smemSet) {
        cudaFuncSetAttribute(k_flash, cudaFuncAttributeMaxDynamicSharedMemorySize, FLASH_SMEM);
        smemSet = 1;
    }

    // ---- embedding + mask packing ----
    k_embed<<<NTOK, 128>>>(in_embed, pos_embed, in_idxs);
    k_packmask<<<BB*LL*HEADS/8, 256>>>(mask);

    // ---- transformer layers ----
    for (int l = 0; l < 4; l++) {
        mgemm(h, NHID, qkv_w + (size_t)l*NHID*QKVD, QKVD, qkv, QKVD,
              NTOK, QKVD, NHID, qkv_b + l*QKVD);
        k_flash<<<dim3(LL/128, BB*HEADS), 256, FLASH_SMEM>>>();
        mgemm(o, NHID, attn_w + (size_t)l*NHID*NHID, NHID, x, NHID,
              NTOK, NHID, NHID, attn_b + l*NHID, h, NHID, 2.0f);
        mgemm(x, NHID, ff1_w + (size_t)l*NHID*FFD, FFD, ff, FFD,
              NTOK, FFD, NHID, ff1_b + l*FFD, nullptr, 0, 0.f, /*relu=*/1);
        mgemm(ff, FFD, ff2_w + (size_t)l*FFD*NHID, NHID, h, NHID,
              NTOK, NHID, FFD, ff2_b + l*NHID, x, NHID, 1.0f);
    }

    // ---- graph preprocessing ----
    k_zero_ints<<<(2*NNODE + 255)/256, 256>>>();
    k_count<<<EE/256, 256>>>(gt_src, gt_dst, 0);
    k_count<<<EE/256, 256>>>(at_src, at_dst, 1);
    k_scan<<<1, 1024>>>(0);
    k_scan<<<1, 1024>>>(1);
    k_scatter<<<EE/256, 256>>>(gt_src, gt_dst, 0);
    k_scatter<<<EE/256, 256>>>(at_src, at_dst, 1);
    k_scales<<<(2*NNODE + 255)/256, 256>>>();
    k_copyxf<<<NNODE, 128>>>();

    // ---- propagations (3 per graph) ----
    int propBlocks = (NNODE + 7) / 8;
    for (int g = 0; g < 2; g++) {
        k_prop_sage<<<propBlocks, 256>>>(xf, P, g);
        k_prop_sage<<<propBlocks, 256>>>(P,  Q, g);
        k_prop_gc  <<<propBlocks, 256>>>(Q,  T + (size_t)g*NNODE*NHID, g);
    }

    // ---- collapse per-head weights: M_i = W1 W2, N_i = M_i W3, c_i, d_i ----
    mgemm(sage1_w, NHID, sage2_w, NHID, Mb, NHID, NHID, NHID, NHID,
          nullptr, nullptr, 0, 0.f, 0, 0, HEADS, 1,
          (long long)NHID*NHID, 0, (long long)NHID*NHID, 0, (long long)NHID*NHID, 0);
    mgemm(Mb, NHID, gc3_w, 64, Nc, 64, NHID, 64, NHID,
          nullptr, nullptr, 0, 0.f, 0, 0, HEADS, 1,
          (long long)NHID*NHID, 0, (long long)NHID*64, 0, (long long)NHID*64, 0);
    {
        GP p; p.A=sage1_b; p.B=sage2_w; p.bias=sage2_b; p.res=nullptr; p.C=cc;
        p.lda=NHID; p.ldb=NHID; p.ldc=NHID; p.ldres=0;
        p.M=1; p.N=NHID; p.K=NHID; p.resScale=0; p.relu=0; p.zDiv=1; p.hmode=0;
        p.aO=NHID; p.bO=(long long)NHID*NHID; p.cO=NHID; p.biasO=NHID;
        p.aI=p.bI=p.cI=p.rO=p.rI=0;
        gemm1_k<<<dim3((NHID+63)/64,1,HEADS), 64>>>(p);
    }
    {
        GP p; p.A=cc; p.B=gc3_w; p.bias=nullptr; p.res=nullptr; p.C=dc;
        p.lda=NHID; p.ldb=64; p.ldc=64; p.ldres=0;
        p.M=1; p.N=64; p.K=NHID; p.resScale=0; p.relu=0; p.zDiv=1; p.hmode=0;
        p.aO=NHID; p.bO=(long long)NHID*64; p.cO=64; p.biasO=0;
        p.aI=p.bI=p.cI=p.rO=p.rI=0;
        gemm1_k<<<dim3(1,1,HEADS), 64>>>(p);
    }

    // ---- xc per head: one launch, A = T[(z>>1)&1], via hmode ----
    mgemm(T, NHID, Nc, 64, xc, NHID,
          NNODE, 64, NHID, nullptr, nullptr, 0, 0.f, 0, 0,
          HEADS, 1,
          0, (long long)NNODE*NHID,
          (long long)NHID*64, 0,
          64, 0, 0, 0, 0, /*hmode=*/1);
    k_xcepi<<<NNODE, 512>>>(gc3_b);

    // ---- final: x = hg + LN(xc); ff = relu(x W1+b) W2 + b; zbar = x + LN(ff) ----
    k_ln_add<<<NNODE, 128>>>(xg, xc, h, /*hgMap=*/1, ln_g, ln_b);
    mgemm(xg, NHID, gff1_w, NHID, fg, NHID, NNODE, NHID, NHID, gff1_b,
          nullptr, 0, 0.f, /*relu=*/1);
    mgemm(fg, NHID, gff2_w, NHID, xc, NHID, NNODE, NHID, NHID, gff2_b);
    k_ln_add<<<NNODE, 128>>>((float*)d_out, xc, xg, /*hgMap=*/0, ln_g, ln_b);

    // ---- zg ----
    if (out_size >= NNODE*NHID + BB*NHID)
        k_zg<<<BB, 128>>>((float*)d_out);
}